// round 1
// baseline (speedup 1.0000x reference)
#include <cuda_runtime.h>

// Problem dims (fixed by the dataset)
#define T_ 4096
#define B_ 8
#define D_ 256
#define P_ 256
#define O_ 256
#define SCALING 0.0625f   // P^-0.5 = 1/16

// Scratch (device globals: allocation-free per harness rules)
__device__ float g_q[(size_t)B_ * T_ * P_];        // [B,T,P] scaled q
__device__ float g_k[(size_t)B_ * T_ * P_];        // [B,T,P]
__device__ float g_v[(size_t)B_ * T_ * P_];        // [B,T,P]
__device__ float g_scores[(size_t)B_ * T_ * T_];   // [B,T,S] 512 MB
__device__ float g_attn[(size_t)T_ * B_ * P_];     // [T,B,P]

// ---------------------------------------------------------------------------
// Generic 128x128x16 SGEMM, 256 threads, 8x8 per-thread micro-tile.
// TRANSB=false: C = A[MxK] * B[KxN]      (B row-major, ldb = N)
// TRANSB=true : C = A[MxK] * B[NxK]^T    (B row-major, ldb = K)
// EPI: 0 = plain store to C
//      1 = QKV split epilogue (bias add, q-scaling, scatter to g_q/g_k/g_v)
//      2 = attn epilogue (scatter to g_attn[T,B,P], batch = blockIdx.z)
//      3 = bias add, store to C
// All dims are exact multiples of the tile sizes -> no bounds checks.
// ---------------------------------------------------------------------------
template<bool TRANSB, int EPI>
__global__ __launch_bounds__(256)
void gemm128(const float* __restrict__ A, const float* __restrict__ B,
             float* __restrict__ C,
             int M, int N, int K, int lda, int ldb, int ldc,
             const float* __restrict__ bias,
             long strideA, long strideB, long strideC)
{
    __shared__ float As[16][128];
    __shared__ float Bs[16][128];

    const int bz = blockIdx.z;
    A += (long)bz * strideA;
    B += (long)bz * strideB;
    C += (long)bz * strideC;

    const int m0 = blockIdx.y * 128;
    const int n0 = blockIdx.x * 128;
    const int tid = threadIdx.x;
    const int tx = tid & 15;        // 0..15 -> 8 output cols each
    const int ty = tid >> 4;        // 0..15 -> 8 output rows each

    float acc[8][8];
#pragma unroll
    for (int i = 0; i < 8; i++)
#pragma unroll
        for (int j = 0; j < 8; j++) acc[i][j] = 0.f;

    for (int k0 = 0; k0 < K; k0 += 16) {
        // ---- load A tile (128 rows x 16 k) with k-major scatter into As[k][m]
#pragma unroll
        for (int i = 0; i < 2; i++) {
            int f   = tid + i * 256;       // 0..511 float4 slots
            int row = f >> 2;              // 0..127
            int kc  = (f & 3) * 4;
            float4 va = *(const float4*)(A + (long)(m0 + row) * lda + k0 + kc);
            As[kc + 0][row] = va.x;
            As[kc + 1][row] = va.y;
            As[kc + 2][row] = va.z;
            As[kc + 3][row] = va.w;
        }
        // ---- load B tile into Bs[k][n]
        if (TRANSB) {
#pragma unroll
            for (int i = 0; i < 2; i++) {
                int f   = tid + i * 256;
                int row = f >> 2;          // 0..127  (n index)
                int kc  = (f & 3) * 4;
                float4 vb = *(const float4*)(B + (long)(n0 + row) * ldb + k0 + kc);
                Bs[kc + 0][row] = vb.x;
                Bs[kc + 1][row] = vb.y;
                Bs[kc + 2][row] = vb.z;
                Bs[kc + 3][row] = vb.w;
            }
        } else {
#pragma unroll
            for (int i = 0; i < 2; i++) {
                int f  = tid + i * 256;
                int kr = f >> 5;           // 0..15
                int nc = (f & 31) * 4;     // 0..124
                float4 vb = *(const float4*)(B + (long)(k0 + kr) * ldb + n0 + nc);
                *(float4*)&Bs[kr][nc] = vb;
            }
        }
        __syncthreads();

        // ---- 8x8 micro-kernel
#pragma unroll
        for (int kk = 0; kk < 16; kk++) {
            float a[8], b[8];
            *(float4*)&a[0] = *(const float4*)&As[kk][ty * 8];
            *(float4*)&a[4] = *(const float4*)&As[kk][ty * 8 + 4];
            *(float4*)&b[0] = *(const float4*)&Bs[kk][tx * 8];
            *(float4*)&b[4] = *(const float4*)&Bs[kk][tx * 8 + 4];
#pragma unroll
            for (int i = 0; i < 8; i++)
#pragma unroll
                for (int j = 0; j < 8; j++)
                    acc[i][j] += a[i] * b[j];
        }
        __syncthreads();
    }

    // ---- epilogue
    const int gnb = n0 + tx * 8;

    if (EPI == 1) {
        // QKV split: global row r = t*B_ + b ; col c in [0, 768)
        // 128-wide tile lies entirely in one of the q/k/v 256-wide segments.
        float bv[8];
#pragma unroll
        for (int j = 0; j < 8; j++) bv[j] = bias[gnb + j];
        const int seg  = gnb >> 8;          // 0=q 1=k 2=v
        const int coff = gnb & 255;
        float* dstbase = (seg == 0) ? g_q : (seg == 1) ? g_k : g_v;
#pragma unroll
        for (int i = 0; i < 8; i++) {
            int gm = m0 + ty * 8 + i;
            int t = gm >> 3;                // / B_
            int b = gm & 7;                 // % B_
            long base = ((long)b * T_ + t) * P_ + coff;
            float o[8];
#pragma unroll
            for (int j = 0; j < 8; j++) {
                o[j] = acc[i][j] + bv[j];
                if (seg == 0) o[j] *= SCALING;
            }
            *(float4*)&dstbase[base]     = *(float4*)&o[0];
            *(float4*)&dstbase[base + 4] = *(float4*)&o[4];
        }
    } else if (EPI == 2) {
        // attn scatter: row gm = t (within batch), col = p
#pragma unroll
        for (int i = 0; i < 8; i++) {
            int gm = m0 + ty * 8 + i;
            long base = ((long)gm * B_ + bz) * P_ + gnb;
            *(float4*)&g_attn[base]     = *(float4*)&acc[i][0];
            *(float4*)&g_attn[base + 4] = *(float4*)&acc[i][4];
        }
    } else if (EPI == 3) {
        float bv[8];
#pragma unroll
        for (int j = 0; j < 8; j++) bv[j] = bias[gnb + j];
#pragma unroll
        for (int i = 0; i < 8; i++) {
            int gm = m0 + ty * 8 + i;
            float o[8];
#pragma unroll
            for (int j = 0; j < 8; j++) o[j] = acc[i][j] + bv[j];
            *(float4*)&C[(long)gm * ldc + gnb]     = *(float4*)&o[0];
            *(float4*)&C[(long)gm * ldc + gnb + 4] = *(float4*)&o[4];
        }
    } else {
#pragma unroll
        for (int i = 0; i < 8; i++) {
            int gm = m0 + ty * 8 + i;
            *(float4*)&C[(long)gm * ldc + gnb]     = *(float4*)&acc[i][0];
            *(float4*)&C[(long)gm * ldc + gnb + 4] = *(float4*)&acc[i][4];
        }
    }
}

// ---------------------------------------------------------------------------
// Row softmax over 4096 elements. One 256-thread block per row, 16 elems/thread
// held in registers (single read, single write of the 512 MB score matrix).
// ---------------------------------------------------------------------------
__global__ __launch_bounds__(256)
void softmax_rows(float* __restrict__ S)
{
    long row = blockIdx.x;
    float* p = S + row * (long)T_;
    int tid  = threadIdx.x;
    int warp = tid >> 5, lane = tid & 31;

    float4 v[4];
    float mx = -3.4e38f;
#pragma unroll
    for (int i = 0; i < 4; i++) {
        v[i] = ((const float4*)p)[i * 256 + tid];
        mx = fmaxf(mx, fmaxf(fmaxf(v[i].x, v[i].y), fmaxf(v[i].z, v[i].w)));
    }
#pragma unroll
    for (int o = 16; o; o >>= 1) mx = fmaxf(mx, __shfl_xor_sync(0xffffffffu, mx, o));

    __shared__ float smax[8], ssum[8];
    if (!lane) smax[warp] = mx;
    __syncthreads();
    float bm = smax[0];
#pragma unroll
    for (int w = 1; w < 8; w++) bm = fmaxf(bm, smax[w]);

    float s = 0.f;
#pragma unroll
    for (int i = 0; i < 4; i++) {
        v[i].x = __expf(v[i].x - bm);
        v[i].y = __expf(v[i].y - bm);
        v[i].z = __expf(v[i].z - bm);
        v[i].w = __expf(v[i].w - bm);
        s += v[i].x + v[i].y + v[i].z + v[i].w;
    }
#pragma unroll
    for (int o = 16; o; o >>= 1) s += __shfl_xor_sync(0xffffffffu, s, o);
    if (!lane) ssum[warp] = s;
    __syncthreads();
    float tot = 0.f;
#pragma unroll
    for (int w = 0; w < 8; w++) tot += ssum[w];
    float inv = 1.0f / tot;

#pragma unroll
    for (int i = 0; i < 4; i++) {
        v[i].x *= inv; v[i].y *= inv; v[i].z *= inv; v[i].w *= inv;
        ((float4*)p)[i * 256 + tid] = v[i];
    }
}

// ---------------------------------------------------------------------------
extern "C" void kernel_launch(void* const* d_in, const int* in_sizes, int n_in,
                              void* d_out, int out_size)
{
    const float* query = (const float*)d_in[0];   // [T,B,D]
    const float* W_kqv = (const float*)d_in[1];   // [D, 3P]
    const float* b_kqv = (const float*)d_in[2];   // [3P]
    const float* W_out = (const float*)d_in[3];   // [P, O]
    const float* b_out = (const float*)d_in[4];   // [O]
    float* out = (float*)d_out;                   // [T,B,O]

    float *q, *k, *v, *sc, *at;
    cudaGetSymbolAddress((void**)&q,  g_q);
    cudaGetSymbolAddress((void**)&k,  g_k);
    cudaGetSymbolAddress((void**)&v,  g_v);
    cudaGetSymbolAddress((void**)&sc, g_scores);
    cudaGetSymbolAddress((void**)&at, g_attn);

    const int MB = T_ * B_;              // 32768
    const long sQKV = (long)T_ * P_;     // per-batch q/k/v stride
    const long sSc  = (long)T_ * T_;     // per-batch score stride

    // 1) QKV projection + split/scale/transpose:  [32768,256] @ [256,768]
    gemm128<false, 1><<<dim3(3 * P_ / 128, MB / 128, 1), 256>>>(
        query, W_kqv, nullptr, MB, 3 * P_, D_, D_, 3 * P_, 0, b_kqv, 0, 0, 0);

    // 2) scores[b] = q[b] @ k[b]^T : per-batch [4096,256] x [4096,256]^T
    gemm128<true, 0><<<dim3(T_ / 128, T_ / 128, B_), 256>>>(
        q, k, sc, T_, T_, P_, P_, P_, T_, nullptr, sQKV, sQKV, sSc);

    // 3) row softmax over the 32768 rows of length 4096
    softmax_rows<<<B_ * T_, 256>>>(sc);

    // 4) attn[b] = probs[b] @ v[b] : [4096,4096] x [4096,256] -> g_attn [T,B,P]
    gemm128<false, 2><<<dim3(P_ / 128, T_ / 128, B_), 256>>>(
        sc, v, nullptr, T_, P_, T_, T_, P_, 0, nullptr, sSc, sQKV, 0);

    // 5) out = attn @ W_out + b_out : [32768,256] @ [256,256]
    gemm128<false, 3><<<dim3(O_ / 128, MB / 128, 1), 256>>>(
        at, W_out, out, MB, O_, P_, P_, O_, O_, b_out, 0, 0, 0);
}

// round 3
// speedup vs baseline: 2.5812x; 2.5812x over previous
#include <cuda_runtime.h>
#include <cstdint>

// Problem dims (fixed by the dataset)
#define T_ 4096
#define B_ 8
#define D_ 256
#define P_ 256
#define O_ 256
#define SCALING 0.0625f   // P^-0.5 = 1/16

// Scratch (device globals: allocation-free per harness rules)
__device__ float g_q[(size_t)B_ * T_ * P_];        // [B,T,P] scaled q
__device__ float g_k[(size_t)B_ * T_ * P_];        // [B,T,P]
__device__ float g_v[(size_t)B_ * T_ * P_];        // [B,T,P]
__device__ float g_vT[(size_t)B_ * P_ * T_];       // [B,P,T]
__device__ float g_scores[(size_t)B_ * T_ * T_];   // [B,T,S] 512 MB
__device__ float g_attn[(size_t)T_ * B_ * P_];     // [T,B,P]
__device__ float g_wkqvT[(size_t)3 * P_ * D_];     // [3P, D]
__device__ float g_woutT[(size_t)O_ * P_];         // [O, P]

// ---------------------------------------------------------------------------
__device__ __forceinline__ uint32_t f2tf32(float f) {
    uint32_t r; asm("cvt.rna.tf32.f32 %0, %1;" : "=r"(r) : "f"(f)); return r;
}
__device__ __forceinline__ void mma8(float* c, const uint32_t* a, const uint32_t* b) {
    asm volatile(
        "mma.sync.aligned.m16n8k8.row.col.f32.tf32.tf32.f32 "
        "{%0,%1,%2,%3}, {%4,%5,%6,%7}, {%8,%9}, {%0,%1,%2,%3};"
        : "+f"(c[0]), "+f"(c[1]), "+f"(c[2]), "+f"(c[3])
        : "r"(a[0]), "r"(a[1]), "r"(a[2]), "r"(a[3]), "r"(b[0]), "r"(b[1]));
}

// ---------------------------------------------------------------------------
// tf32 mma.sync GEMM: CTA tile 128x128, K-chunk 32, double-buffered smem with
// register prefetch. A [M,K] K-major (lda), B [N,K] K-major (ldb): D = A @ B^T.
// 8 warps: wm = w&3 (4 x 32 rows), wn = w>>2 (2 x 64 cols).
// Smem layout per tile: row-major [128][32] floats with SW128 XOR swizzle.
// EPI: 0=plain C store, 1=QKV split (+bias, q-scale, scatter), 2=attn scatter,
//      3=bias + C store
// ---------------------------------------------------------------------------
#define SM_BYTES 65536   // 2 x (16KB A + 16KB B)

template<int EPI>
__global__ void __launch_bounds__(256)
gemm_mma(const float* __restrict__ A, const float* __restrict__ Bm,
         float* __restrict__ C, int K, int lda, int ldb, int ldc,
         const float* __restrict__ bias, long sA, long sB, long sC)
{
    extern __shared__ char smem[];
    const int tid = threadIdx.x;
    const int w = tid >> 5, lane = tid & 31;
    const int wm = w & 3, wn = w >> 2;
    const int lane4 = lane >> 2, lanek = lane & 3;
    const int m0 = blockIdx.y * 128, n0 = blockIdx.x * 128, bz = blockIdx.z;

    A  += (long)bz * sA + (long)m0 * lda;
    Bm += (long)bz * sB + (long)n0 * ldb;
    C  += (long)bz * sC;

    float acc[16][4];
#pragma unroll
    for (int i = 0; i < 16; i++)
#pragma unroll
        for (int j = 0; j < 4; j++) acc[i][j] = 0.f;

    float4 pa[4], pb[4];
    const int NC = K / 32;

    // prefetch chunk 0
#pragma unroll
    for (int i = 0; i < 4; i++) {
        int f = tid + i * 256, m = f >> 3, kq = f & 7;
        pa[i] = *(const float4*)(A  + (long)m * lda + kq * 4);
        pb[i] = *(const float4*)(Bm + (long)m * ldb + kq * 4);
    }

    for (int c = 0; c < NC; ++c) {
        const int s = c & 1;
        // store prefetched chunk into smem buffer s (cvt to tf32, swizzled)
#pragma unroll
        for (int i = 0; i < 4; i++) {
            int f = tid + i * 256, m = f >> 3, kq = f & 7;
            uint32_t off = (uint32_t)(m * 128 + ((kq * 16) ^ ((m & 7) * 16)));
            uint32_t* ap = (uint32_t*)(smem + s * 16384 + off);
            ap[0] = f2tf32(pa[i].x); ap[1] = f2tf32(pa[i].y);
            ap[2] = f2tf32(pa[i].z); ap[3] = f2tf32(pa[i].w);
            uint32_t* bp = (uint32_t*)(smem + 32768 + s * 16384 + off);
            bp[0] = f2tf32(pb[i].x); bp[1] = f2tf32(pb[i].y);
            bp[2] = f2tf32(pb[i].z); bp[3] = f2tf32(pb[i].w);
        }
        __syncthreads();

        // prefetch next chunk
        if (c + 1 < NC) {
            const float* Ag = A  + (c + 1) * 32;
            const float* Bg = Bm + (c + 1) * 32;
#pragma unroll
            for (int i = 0; i < 4; i++) {
                int f = tid + i * 256, m = f >> 3, kq = f & 7;
                pa[i] = *(const float4*)(Ag + (long)m * lda + kq * 4);
                pb[i] = *(const float4*)(Bg + (long)m * ldb + kq * 4);
            }
        }

        // compute from buffer s
        const char* aB = smem + s * 16384;
        const char* bB = smem + 32768 + s * 16384;
        const uint32_t sw = (uint32_t)(lane4 * 16);
#pragma unroll
        for (int kk = 0; kk < 4; ++kk) {
            const int c0 = kk * 8 + lanek;
            const uint32_t o0 = (uint32_t)(4 * c0) ^ sw;
            const uint32_t o1 = (uint32_t)(4 * (c0 + 4)) ^ sw;
            uint32_t af[2][4];
#pragma unroll
            for (int mt = 0; mt < 2; ++mt) {
                const char* base = aB + (wm * 32 + mt * 16 + lane4) * 128;
                af[mt][0] = *(const uint32_t*)(base + o0);
                af[mt][1] = *(const uint32_t*)(base + 1024 + o0);
                af[mt][2] = *(const uint32_t*)(base + o1);
                af[mt][3] = *(const uint32_t*)(base + 1024 + o1);
            }
            uint32_t bf[8][2];
#pragma unroll
            for (int nt = 0; nt < 8; ++nt) {
                const char* base = bB + (wn * 64 + nt * 8 + lane4) * 128;
                bf[nt][0] = *(const uint32_t*)(base + o0);
                bf[nt][1] = *(const uint32_t*)(base + o1);
            }
#pragma unroll
            for (int mt = 0; mt < 2; ++mt)
#pragma unroll
                for (int nt = 0; nt < 8; ++nt)
                    mma8(acc[mt * 8 + nt], af[mt], bf[nt]);
        }
        __syncthreads();
    }

    // ---- epilogue
    const int rb = m0 + wm * 32 + lane4;
    const int cb = n0 + wn * 64 + 2 * lanek;
#pragma unroll
    for (int mt = 0; mt < 2; ++mt) {
        const int r = rb + mt * 16;
#pragma unroll
        for (int nt = 0; nt < 8; ++nt) {
            float* a4 = acc[mt * 8 + nt];
            const int gc = cb + nt * 8;
            if (EPI == 0) {
                *(float2*)(C + (long)r * ldc + gc)       = make_float2(a4[0], a4[1]);
                *(float2*)(C + (long)(r + 8) * ldc + gc) = make_float2(a4[2], a4[3]);
            } else if (EPI == 1) {
                const int seg = gc >> 8, col = gc & 255;
                float2 bv = *(const float2*)(bias + gc);
                const float scl = (seg == 0) ? SCALING : 1.0f;
                float* dstb = (seg == 0 ? g_q : (seg == 1 ? g_k : g_v));
                int t0 = r >> 3, b0 = r & 7;
                *(float2*)(dstb + ((long)b0 * T_ + t0) * P_ + col) =
                    make_float2((a4[0] + bv.x) * scl, (a4[1] + bv.y) * scl);
                int t1 = (r + 8) >> 3, b1 = (r + 8) & 7;
                *(float2*)(dstb + ((long)b1 * T_ + t1) * P_ + col) =
                    make_float2((a4[2] + bv.x) * scl, (a4[3] + bv.y) * scl);
            } else if (EPI == 2) {
                *(float2*)(g_attn + ((long)r * B_ + bz) * P_ + gc) =
                    make_float2(a4[0], a4[1]);
                *(float2*)(g_attn + ((long)(r + 8) * B_ + bz) * P_ + gc) =
                    make_float2(a4[2], a4[3]);
            } else {
                float2 bv = *(const float2*)(bias + gc);
                *(float2*)(C + (long)r * ldc + gc) =
                    make_float2(a4[0] + bv.x, a4[1] + bv.y);
                *(float2*)(C + (long)(r + 8) * ldc + gc) =
                    make_float2(a4[2] + bv.x, a4[3] + bv.y);
            }
        }
    }
}

// ---------------------------------------------------------------------------
// Batched 32x32 tiled transpose: src [z][R][C] -> dst [z][C][R]
// ---------------------------------------------------------------------------
__global__ __launch_bounds__(256)
void transpose_k(const float* __restrict__ src, float* __restrict__ dst,
                 int R, int C, long sS, long sD)
{
    __shared__ float tile[32][33];
    src += (long)blockIdx.z * sS;
    dst += (long)blockIdx.z * sD;
    const int c0 = blockIdx.x * 32, r0 = blockIdx.y * 32;
    const int x = threadIdx.x, y = threadIdx.y;
#pragma unroll
    for (int i = 0; i < 32; i += 8)
        tile[y + i][x] = src[(long)(r0 + y + i) * C + c0 + x];
    __syncthreads();
#pragma unroll
    for (int i = 0; i < 32; i += 8)
        dst[(long)(c0 + y + i) * R + r0 + x] = tile[x][y + i];
}

// ---------------------------------------------------------------------------
// Row softmax over 4096 elements (registers, single read + single write)
// ---------------------------------------------------------------------------
__global__ __launch_bounds__(256)
void softmax_rows(float* __restrict__ S)
{
    long row = blockIdx.x;
    float* p = S + row * (long)T_;
    int tid = threadIdx.x;
    int warp = tid >> 5, lane = tid & 31;

    float4 v[4];
    float mx = -3.4e38f;
#pragma unroll
    for (int i = 0; i < 4; i++) {
        v[i] = ((const float4*)p)[i * 256 + tid];
        mx = fmaxf(mx, fmaxf(fmaxf(v[i].x, v[i].y), fmaxf(v[i].z, v[i].w)));
    }
#pragma unroll
    for (int o = 16; o; o >>= 1) mx = fmaxf(mx, __shfl_xor_sync(0xffffffffu, mx, o));

    __shared__ float smax[8], ssum[8];
    if (!lane) smax[warp] = mx;
    __syncthreads();
    float bm = smax[0];
#pragma unroll
    for (int w2 = 1; w2 < 8; w2++) bm = fmaxf(bm, smax[w2]);

    float s = 0.f;
#pragma unroll
    for (int i = 0; i < 4; i++) {
        v[i].x = __expf(v[i].x - bm);
        v[i].y = __expf(v[i].y - bm);
        v[i].z = __expf(v[i].z - bm);
        v[i].w = __expf(v[i].w - bm);
        s += v[i].x + v[i].y + v[i].z + v[i].w;
    }
#pragma unroll
    for (int o = 16; o; o >>= 1) s += __shfl_xor_sync(0xffffffffu, s, o);
    if (!lane) ssum[warp] = s;
    __syncthreads();
    float tot = 0.f;
#pragma unroll
    for (int w2 = 0; w2 < 8; w2++) tot += ssum[w2];
    float inv = 1.0f / tot;

#pragma unroll
    for (int i = 0; i < 4; i++) {
        v[i].x *= inv; v[i].y *= inv; v[i].z *= inv; v[i].w *= inv;
        ((float4*)p)[i * 256 + tid] = v[i];
    }
}

// ---------------------------------------------------------------------------
extern "C" void kernel_launch(void* const* d_in, const int* in_sizes, int n_in,
                              void* d_out, int out_size)
{
    const float* query = (const float*)d_in[0];   // [T,B,D]
    const float* W_kqv = (const float*)d_in[1];   // [D, 3P]
    const float* b_kqv = (const float*)d_in[2];   // [3P]
    const float* W_out = (const float*)d_in[3];   // [P, O]
    const float* b_out = (const float*)d_in[4];   // [O]
    float* out = (float*)d_out;                   // [T,B,O]

    float *q, *k, *v, *vT, *sc, *at, *wkqvT, *woutT;
    cudaGetSymbolAddress((void**)&q,     g_q);
    cudaGetSymbolAddress((void**)&k,     g_k);
    cudaGetSymbolAddress((void**)&v,     g_v);
    cudaGetSymbolAddress((void**)&vT,    g_vT);
    cudaGetSymbolAddress((void**)&sc,    g_scores);
    cudaGetSymbolAddress((void**)&at,    g_attn);
    cudaGetSymbolAddress((void**)&wkqvT, g_wkqvT);
    cudaGetSymbolAddress((void**)&woutT, g_woutT);

    cudaFuncSetAttribute(gemm_mma<0>, cudaFuncAttributeMaxDynamicSharedMemorySize, SM_BYTES);
    cudaFuncSetAttribute(gemm_mma<1>, cudaFuncAttributeMaxDynamicSharedMemorySize, SM_BYTES);
    cudaFuncSetAttribute(gemm_mma<2>, cudaFuncAttributeMaxDynamicSharedMemorySize, SM_BYTES);
    cudaFuncSetAttribute(gemm_mma<3>, cudaFuncAttributeMaxDynamicSharedMemorySize, SM_BYTES);

    const long sQKV = (long)T_ * P_;   // per-batch q/k/v stride
    const long sSc  = (long)T_ * T_;   // per-batch score stride
    const dim3 tb(32, 8);

    // 0) transpose weights to [N,K] K-major
    transpose_k<<<dim3(3 * P_ / 32, D_ / 32, 1), tb>>>(W_kqv, wkqvT, D_, 3 * P_, 0, 0);
    transpose_k<<<dim3(O_ / 32, P_ / 32, 1), tb>>>(W_out, woutT, P_, O_, 0, 0);

    // 1) QKV projection + split/scale/transpose: [32768,256] @ [768,256]^T
    gemm_mma<1><<<dim3(6, 256, 1), 256, SM_BYTES>>>(
        query, wkqvT, nullptr, D_, D_, D_, 0, b_kqv, 0, 0, 0);

    // 2) transpose v -> [B,P,T]
    transpose_k<<<dim3(P_ / 32, T_ / 32, B_), tb>>>(v, vT, T_, P_, sQKV, (long)P_ * T_);

    // 3) scores[b] = q[b] @ k[b]^T : [4096,256] @ [4096,256]^T
    gemm_mma<0><<<dim3(32, 32, 8), 256, SM_BYTES>>>(
        q, k, sc, P_, P_, P_, T_, nullptr, sQKV, sQKV, sSc);

    // 4) softmax rows
    softmax_rows<<<B_ * T_, 256>>>(sc);

    // 5) attn[b] = probs[b] @ vT[b]^T : [4096,4096] @ [256,4096]^T -> g_attn
    gemm_mma<2><<<dim3(2, 32, 8), 256, SM_BYTES>>>(
        sc, vT, nullptr, T_, T_, T_, 0, nullptr, sSc, (long)P_ * T_, 0);

    // 6) out = attn @ woutT^T + b_out : [32768,256] @ [256,256]^T
    gemm_mma<3><<<dim3(2, 256, 1), 256, SM_BYTES>>>(
        at, woutT, out, P_, P_, P_, O_, b_out, 0, 0, 0);
}

// round 4
// speedup vs baseline: 3.0501x; 1.1817x over previous
#include <cuda_runtime.h>
#include <cstdint>

// Problem dims (fixed by the dataset)
#define T_ 4096
#define B_ 8
#define D_ 256
#define P_ 256
#define O_ 256
#define SCALING 0.0625f   // P^-0.5 = 1/16
#define QT 64             // q rows per flash CTA
#define KT 128            // kv per flash tile
#define NTILE (T_ / KT)   // 32

// Scratch (device globals: allocation-free per harness rules)
__device__ float g_q[(size_t)B_ * T_ * P_];        // [B,T,P] scaled q (tf32-rounded)
__device__ float g_k[(size_t)B_ * T_ * P_];        // [B,T,P] (tf32-rounded)
__device__ float g_v[(size_t)B_ * T_ * P_];        // [B,T,P] (tf32-rounded)
__device__ float g_vT[(size_t)B_ * P_ * T_];       // [B,P,T]
__device__ float g_attn[(size_t)T_ * B_ * P_];     // [T,B,P]
__device__ float g_wkqvT[(size_t)3 * P_ * D_];     // [3P, D]
__device__ float g_woutT[(size_t)O_ * P_];         // [O, P]

// ---------------------------------------------------------------------------
__device__ __forceinline__ uint32_t f2tf32(float f) {
    uint32_t r; asm("cvt.rna.tf32.f32 %0, %1;" : "=r"(r) : "f"(f)); return r;
}
__device__ __forceinline__ float ftf(float f) {
    return __uint_as_float(f2tf32(f));
}
__device__ __forceinline__ void mma8(float* c, const uint32_t* a, const uint32_t* b) {
    asm volatile(
        "mma.sync.aligned.m16n8k8.row.col.f32.tf32.tf32.f32 "
        "{%0,%1,%2,%3}, {%4,%5,%6,%7}, {%8,%9}, {%0,%1,%2,%3};"
        : "+f"(c[0]), "+f"(c[1]), "+f"(c[2]), "+f"(c[3])
        : "r"(a[0]), "r"(a[1]), "r"(a[2]), "r"(a[3]), "r"(b[0]), "r"(b[1]));
}
__device__ __forceinline__ uint32_t smem_u32(const void* p) {
    uint32_t a;
    asm("{ .reg .u64 t; cvta.to.shared.u64 t, %1; cvt.u32.u64 %0, t; }" : "=r"(a) : "l"(p));
    return a;
}
__device__ __forceinline__ void cpa16(uint32_t dst, const void* src) {
    asm volatile("cp.async.cg.shared.global [%0], [%1], 16;" :: "r"(dst), "l"(src));
}
#define CP_COMMIT() asm volatile("cp.async.commit_group;" ::: "memory")
#define CP_WAIT1()  asm volatile("cp.async.wait_group 1;" ::: "memory")
#define CP_WAIT0()  asm volatile("cp.async.wait_group 0;" ::: "memory")

// ---------------------------------------------------------------------------
// tf32 mma.sync GEMM (from R3): CTA tile 128x128, K-chunk 32, double-buffered.
// A [M,K] K-major, B [N,K] K-major: D = A @ B^T.
// EPI: 1=QKV split (+bias, q-scale, tf32-round, scatter), 3=bias + C store
// ---------------------------------------------------------------------------
#define SMG_BYTES 65536

template<int EPI>
__global__ void __launch_bounds__(256)
gemm_mma(const float* __restrict__ A, const float* __restrict__ Bm,
         float* __restrict__ C, int K, int lda, int ldb, int ldc,
         const float* __restrict__ bias)
{
    extern __shared__ char smem[];
    const int tid = threadIdx.x;
    const int w = tid >> 5, lane = tid & 31;
    const int wm = w & 3, wn = w >> 2;
    const int lane4 = lane >> 2, lanek = lane & 3;
    const int m0 = blockIdx.y * 128, n0 = blockIdx.x * 128;

    A  += (long)m0 * lda;
    Bm += (long)n0 * ldb;

    float acc[16][4];
#pragma unroll
    for (int i = 0; i < 16; i++)
#pragma unroll
        for (int j = 0; j < 4; j++) acc[i][j] = 0.f;

    float4 pa[4], pb[4];
    const int NC = K / 32;
#pragma unroll
    for (int i = 0; i < 4; i++) {
        int f = tid + i * 256, m = f >> 3, kq = f & 7;
        pa[i] = *(const float4*)(A  + (long)m * lda + kq * 4);
        pb[i] = *(const float4*)(Bm + (long)m * ldb + kq * 4);
    }

    for (int c = 0; c < NC; ++c) {
        const int s = c & 1;
#pragma unroll
        for (int i = 0; i < 4; i++) {
            int f = tid + i * 256, m = f >> 3, kq = f & 7;
            uint32_t off = (uint32_t)(m * 128 + ((kq * 16) ^ ((m & 7) * 16)));
            uint32_t* ap = (uint32_t*)(smem + s * 16384 + off);
            ap[0] = f2tf32(pa[i].x); ap[1] = f2tf32(pa[i].y);
            ap[2] = f2tf32(pa[i].z); ap[3] = f2tf32(pa[i].w);
            uint32_t* bp = (uint32_t*)(smem + 32768 + s * 16384 + off);
            bp[0] = f2tf32(pb[i].x); bp[1] = f2tf32(pb[i].y);
            bp[2] = f2tf32(pb[i].z); bp[3] = f2tf32(pb[i].w);
        }
        __syncthreads();
        if (c + 1 < NC) {
            const float* Ag = A  + (c + 1) * 32;
            const float* Bg = Bm + (c + 1) * 32;
#pragma unroll
            for (int i = 0; i < 4; i++) {
                int f = tid + i * 256, m = f >> 3, kq = f & 7;
                pa[i] = *(const float4*)(Ag + (long)m * lda + kq * 4);
                pb[i] = *(const float4*)(Bg + (long)m * ldb + kq * 4);
            }
        }
        const char* aB = smem + s * 16384;
        const char* bB = smem + 32768 + s * 16384;
        const uint32_t sw = (uint32_t)(lane4 * 16);
#pragma unroll
        for (int kk = 0; kk < 4; ++kk) {
            const int c0 = kk * 8 + lanek;
            const uint32_t o0 = (uint32_t)(4 * c0) ^ sw;
            const uint32_t o1 = (uint32_t)(4 * (c0 + 4)) ^ sw;
            uint32_t af[2][4];
#pragma unroll
            for (int mt = 0; mt < 2; ++mt) {
                const char* base = aB + (wm * 32 + mt * 16 + lane4) * 128;
                af[mt][0] = *(const uint32_t*)(base + o0);
                af[mt][1] = *(const uint32_t*)(base + 1024 + o0);
                af[mt][2] = *(const uint32_t*)(base + o1);
                af[mt][3] = *(const uint32_t*)(base + 1024 + o1);
            }
            uint32_t bf[8][2];
#pragma unroll
            for (int nt = 0; nt < 8; ++nt) {
                const char* base = bB + (wn * 64 + nt * 8 + lane4) * 128;
                bf[nt][0] = *(const uint32_t*)(base + o0);
                bf[nt][1] = *(const uint32_t*)(base + o1);
            }
#pragma unroll
            for (int mt = 0; mt < 2; ++mt)
#pragma unroll
                for (int nt = 0; nt < 8; ++nt)
                    mma8(acc[mt * 8 + nt], af[mt], bf[nt]);
        }
        __syncthreads();
    }

    const int rb = m0 + wm * 32 + lane4;
    const int cb = n0 + wn * 64 + 2 * lanek;
#pragma unroll
    for (int mt = 0; mt < 2; ++mt) {
        const int r = rb + mt * 16;
#pragma unroll
        for (int nt = 0; nt < 8; ++nt) {
            float* a4 = acc[mt * 8 + nt];
            const int gc = cb + nt * 8;
            if (EPI == 1) {
                const int seg = gc >> 8, col = gc & 255;
                float2 bv = *(const float2*)(bias + gc);
                const float scl = (seg == 0) ? SCALING : 1.0f;
                float* dstb = (seg == 0 ? g_q : (seg == 1 ? g_k : g_v));
                int t0 = r >> 3, b0 = r & 7;
                *(float2*)(dstb + ((long)b0 * T_ + t0) * P_ + col) =
                    make_float2(ftf((a4[0] + bv.x) * scl), ftf((a4[1] + bv.y) * scl));
                int t1 = (r + 8) >> 3, b1 = (r + 8) & 7;
                *(float2*)(dstb + ((long)b1 * T_ + t1) * P_ + col) =
                    make_float2(ftf((a4[2] + bv.x) * scl), ftf((a4[3] + bv.y) * scl));
            } else {
                float2 bv = *(const float2*)(bias + gc);
                *(float2*)(C + (long)r * ldc + gc) =
                    make_float2(a4[0] + bv.x, a4[1] + bv.y);
                *(float2*)(C + (long)(r + 8) * ldc + gc) =
                    make_float2(a4[2] + bv.x, a4[3] + bv.y);
            }
        }
    }
}

// ---------------------------------------------------------------------------
// Batched 32x32 tiled transpose
// ---------------------------------------------------------------------------
__global__ __launch_bounds__(256)
void transpose_k(const float* __restrict__ src, float* __restrict__ dst,
                 int R, int C, long sS, long sD)
{
    __shared__ float tile[32][33];
    src += (long)blockIdx.z * sS;
    dst += (long)blockIdx.z * sD;
    const int c0 = blockIdx.x * 32, r0 = blockIdx.y * 32;
    const int x = threadIdx.x, y = threadIdx.y;
#pragma unroll
    for (int i = 0; i < 32; i += 8)
        tile[y + i][x] = src[(long)(r0 + y + i) * C + c0 + x];
    __syncthreads();
#pragma unroll
    for (int i = 0; i < 32; i += 8)
        dst[(long)(c0 + y + i) * R + r0 + x] = tile[x][y + i];
}

// ---------------------------------------------------------------------------
// Flash attention: per CTA = 64 q rows x one batch. kv tiles of 128.
// smem: Q resident 64KB | K 3x16KB (cp.async triple) | V 2x32KB (cp.async
// double) | P 32KB | stats. Online softmax; O accum in regs (64/thread).
// S warps: wm=w&1 (32 rows), wn=w>>1 (32 kv cols).
// PV warps: wm=w&1 (32 rows), wn=w>>1 (64 d cols).
// ---------------------------------------------------------------------------
#define SM_Q    0
#define SM_K    65536
#define SM_V    (SM_K + 3 * 16384)
#define SM_P    (SM_V + 2 * 32768)
#define SM_ST   (SM_P + 32768)
#define SMF_BYTES (SM_ST + 2816)
// stats: pmax[4][64] @ +0, psum[4][64] @ +1024, m[64] @ +2048,
//        l[64] @ +2304, scale[64] @ +2560

__global__ void __launch_bounds__(256, 1)
flash_attn()
{
    extern __shared__ char smem[];
    const uint32_t sb = smem_u32(smem);
    const int tid = threadIdx.x;
    const int w = tid >> 5, lane = tid & 31;
    const int wm = w & 1, wn = w >> 1;
    const int lane4 = lane >> 2, lanek = lane & 3;
    const int bz = blockIdx.y;
    const int t0 = blockIdx.x * QT;

    const float* qb  = g_q  + ((long)bz * T_ + t0) * P_;
    const float* kb  = g_k  + (long)bz * T_ * P_;
    const float* vtb = g_vT + (long)bz * P_ * T_;

    float* pmax  = (float*)(smem + SM_ST);
    float* psum  = (float*)(smem + SM_ST + 1024);
    float* m_st  = (float*)(smem + SM_ST + 2048);
    float* l_st  = (float*)(smem + SM_ST + 2304);
    float* sc_st = (float*)(smem + SM_ST + 2560);

    // ---- load Q resident (already tf32-rounded), 8 chunk-blocks [64][32]
#pragma unroll
    for (int i = 0; i < 16; i++) {
        int f = tid + i * 256;
        int r = f >> 6, kq = f & 63;
        float4 v = *(const float4*)(qb + (long)r * P_ + kq * 4);
        uint32_t off = (uint32_t)((kq >> 3) * 8192 + r * 128 + (((kq & 7) * 16) ^ ((r & 7) * 16)));
        *(float4*)(smem + SM_Q + off) = v;
    }
    if (tid < QT) { m_st[tid] = -3.4e38f; l_st[tid] = 0.f; }

    // O accumulator: rows wm*32+mt*16+lane4(+8), cols wn*64+nt*8+2lanek(+1)
    float acco[2][8][4];
#pragma unroll
    for (int mt = 0; mt < 2; mt++)
#pragma unroll
        for (int nt = 0; nt < 8; nt++)
#pragma unroll
            for (int e = 0; e < 4; e++) acco[mt][nt][e] = 0.f;

    // prologue: issue K(0,0), K(0,1)
#pragma unroll
    for (int pc = 0; pc < 2; pc++) {
#pragma unroll
        for (int i = 0; i < 4; i++) {
            int f = tid + i * 256, r = f >> 3, kq = f & 7;
            uint32_t dst = sb + SM_K + pc * 16384 +
                           (uint32_t)(r * 128 + ((kq * 16) ^ ((r & 7) * 16)));
            cpa16(dst, kb + (long)r * P_ + pc * 32 + kq * 4);
        }
        CP_COMMIT();
    }

    const uint32_t sw = (uint32_t)(lane4 * 16);

    for (int j = 0; j < NTILE; ++j) {
        const float* kbj = kb + (long)j * KT * P_;

        // ================= S phase: S[64x128] = Qtile @ Kj^T ==============
        float accs[2][4][4];
#pragma unroll
        for (int mt = 0; mt < 2; mt++)
#pragma unroll
            for (int nt = 0; nt < 4; nt++)
#pragma unroll
                for (int e = 0; e < 4; e++) accs[mt][nt][e] = 0.f;

        for (int c = 0; c < 8; ++c) {
            CP_WAIT1();
            __syncthreads();
            // issue next: K chunk c+2 (same tile) or V chunk 0/1
            if (c < 6) {
#pragma unroll
                for (int i = 0; i < 4; i++) {
                    int f = tid + i * 256, r = f >> 3, kq = f & 7;
                    uint32_t dst = sb + SM_K + ((c + 2) % 3) * 16384 +
                                   (uint32_t)(r * 128 + ((kq * 16) ^ ((r & 7) * 16)));
                    cpa16(dst, kbj + (long)r * P_ + (c + 2) * 32 + kq * 4);
                }
            } else {
                const int d = c - 6;  // V chunk 0 or 1
#pragma unroll
                for (int i = 0; i < 8; i++) {
                    int f = tid + i * 256, n = f >> 3, kq = f & 7;
                    uint32_t dst = sb + SM_V + d * 32768 +
                                   (uint32_t)(n * 128 + ((kq * 16) ^ ((n & 7) * 16)));
                    cpa16(dst, vtb + (long)n * T_ + j * KT + d * 32 + kq * 4);
                }
            }
            CP_COMMIT();

            // compute chunk c: A = Q block c, B = K buf c%3
            const char* aB = smem + SM_Q + c * 8192;
            const char* bB = smem + SM_K + (c % 3) * 16384;
#pragma unroll
            for (int kk = 0; kk < 4; ++kk) {
                const int c0 = kk * 8 + lanek;
                const uint32_t o0 = (uint32_t)(4 * c0) ^ sw;
                const uint32_t o1 = (uint32_t)(4 * (c0 + 4)) ^ sw;
                uint32_t af[2][4];
#pragma unroll
                for (int mt = 0; mt < 2; ++mt) {
                    const char* base = aB + (wm * 32 + mt * 16 + lane4) * 128;
                    af[mt][0] = *(const uint32_t*)(base + o0);
                    af[mt][1] = *(const uint32_t*)(base + 1024 + o0);
                    af[mt][2] = *(const uint32_t*)(base + o1);
                    af[mt][3] = *(const uint32_t*)(base + 1024 + o1);
                }
                uint32_t bf[4][2];
#pragma unroll
                for (int nt = 0; nt < 4; ++nt) {
                    const char* base = bB + (wn * 32 + nt * 8 + lane4) * 128;
                    bf[nt][0] = *(const uint32_t*)(base + o0);
                    bf[nt][1] = *(const uint32_t*)(base + o1);
                }
#pragma unroll
                for (int mt = 0; mt < 2; ++mt)
#pragma unroll
                    for (int nt = 0; nt < 4; ++nt)
                        mma8(accs[mt][nt], af[mt], bf[nt]);
            }
        }

        // ================= online softmax =================================
        // rows per thread: r(mt,h) = wm*32 + mt*16 + lane4 + 8h
        // 1. partial row max over this warp's 32 kv cols
#pragma unroll
        for (int mt = 0; mt < 2; mt++) {
#pragma unroll
            for (int h = 0; h < 2; h++) {
                float mx = -3.4e38f;
#pragma unroll
                for (int nt = 0; nt < 4; nt++)
                    mx = fmaxf(mx, fmaxf(accs[mt][nt][2 * h], accs[mt][nt][2 * h + 1]));
                mx = fmaxf(mx, __shfl_xor_sync(0xffffffffu, mx, 1));
                mx = fmaxf(mx, __shfl_xor_sync(0xffffffffu, mx, 2));
                if (lanek == 0)
                    pmax[wn * 64 + wm * 32 + mt * 16 + lane4 + 8 * h] = mx;
            }
        }
        __syncthreads();
        if (tid < QT) {
            float mo = m_st[tid];
            float mn = fmaxf(fmaxf(pmax[tid], pmax[64 + tid]),
                             fmaxf(pmax[128 + tid], pmax[192 + tid]));
            mn = fmaxf(mo, mn);
            m_st[tid] = mn;
            sc_st[tid] = __expf(mo - mn);
        }
        __syncthreads();

        // 2. exp, P write (tf32), partial row sums ; 3. rescale O
#pragma unroll
        for (int mt = 0; mt < 2; mt++) {
#pragma unroll
            for (int h = 0; h < 2; h++) {
                const int r = wm * 32 + mt * 16 + lane4 + 8 * h;
                const float m = m_st[r];
                float s = 0.f;
#pragma unroll
                for (int nt = 0; nt < 4; nt++) {
                    float e0 = __expf(accs[mt][nt][2 * h] - m);
                    float e1 = __expf(accs[mt][nt][2 * h + 1] - m);
                    s += e0 + e1;
                    const int cw = nt * 8 + 2 * lanek;  // col within 32-kv block wn
                    uint32_t off = (uint32_t)(r * 128 + (((cw >> 2) * 16) ^ ((r & 7) * 16)) + (cw & 3) * 4);
                    uint32_t* pp = (uint32_t*)(smem + SM_P + wn * 8192 + off);
                    pp[0] = f2tf32(e0); pp[1] = f2tf32(e1);
                }
                s += __shfl_xor_sync(0xffffffffu, s, 1);
                s += __shfl_xor_sync(0xffffffffu, s, 2);
                if (lanek == 0) psum[wn * 64 + r] = s;
                const float scl = sc_st[r];
#pragma unroll
                for (int nt = 0; nt < 8; nt++) {
                    acco[mt][nt][2 * h]     *= scl;
                    acco[mt][nt][2 * h + 1] *= scl;
                }
            }
        }
        __syncthreads();
        if (tid < QT)
            l_st[tid] = l_st[tid] * sc_st[tid] +
                        (psum[tid] + psum[64 + tid] + psum[128 + tid] + psum[192 + tid]);

        // ================= PV phase: O += P[64x128] @ Vj ==================
        for (int d = 0; d < 4; ++d) {
            CP_WAIT1();
            __syncthreads();
            const char* aB = smem + SM_P + d * 8192;
            const char* bB = smem + SM_V + (d & 1) * 32768;
#pragma unroll
            for (int kk = 0; kk < 4; ++kk) {
                const int c0 = kk * 8 + lanek;
                const uint32_t o0 = (uint32_t)(4 * c0) ^ sw;
                const uint32_t o1 = (uint32_t)(4 * (c0 + 4)) ^ sw;
                uint32_t af[2][4];
#pragma unroll
                for (int mt = 0; mt < 2; ++mt) {
                    const char* base = aB + (wm * 32 + mt * 16 + lane4) * 128;
                    af[mt][0] = *(const uint32_t*)(base + o0);
                    af[mt][1] = *(const uint32_t*)(base + 1024 + o0);
                    af[mt][2] = *(const uint32_t*)(base + o1);
                    af[mt][3] = *(const uint32_t*)(base + 1024 + o1);
                }
                uint32_t bf[8][2];
#pragma unroll
                for (int nt = 0; nt < 8; ++nt) {
                    const char* base = bB + (wn * 64 + nt * 8 + lane4) * 128;
                    bf[nt][0] = *(const uint32_t*)(base + o0);
                    bf[nt][1] = *(const uint32_t*)(base + o1);
                }
#pragma unroll
                for (int mt = 0; mt < 2; ++mt)
#pragma unroll
                    for (int nt = 0; nt < 8; ++nt)
                        mma8(acco[mt][nt], af[mt], bf[nt]);
            }
            __syncthreads();
            // issue: V chunk d+2 (buf (d+2)&1 == d&1, safe post-barrier),
            // or K chunks 0/1 of next tile
            if (d < 2) {
#pragma unroll
                for (int i = 0; i < 8; i++) {
                    int f = tid + i * 256, n = f >> 3, kq = f & 7;
                    uint32_t dst = sb + SM_V + (d & 1) * 32768 +
                                   (uint32_t)(n * 128 + ((kq * 16) ^ ((n & 7) * 16)));
                    cpa16(dst, vtb + (long)n * T_ + j * KT + (d + 2) * 32 + kq * 4);
                }
            } else {
                const int jn = (j + 1) & (NTILE - 1);
                const float* kbn = kb + (long)jn * KT * P_;
                const int cn = d - 2;
#pragma unroll
                for (int i = 0; i < 4; i++) {
                    int f = tid + i * 256, r = f >> 3, kq = f & 7;
                    uint32_t dst = sb + SM_K + (cn % 3) * 16384 +
                                   (uint32_t)(r * 128 + ((kq * 16) ^ ((r & 7) * 16)));
                    cpa16(dst, kbn + (long)r * P_ + cn * 32 + kq * 4);
                }
            }
            CP_COMMIT();
        }
    }

    CP_WAIT0();
    __syncthreads();

    // ---- epilogue: O / l -> g_attn [T,B,P]
#pragma unroll
    for (int mt = 0; mt < 2; mt++) {
#pragma unroll
        for (int h = 0; h < 2; h++) {
            const int r = wm * 32 + mt * 16 + lane4 + 8 * h;
            const float inv = 1.0f / l_st[r];
            const long base = ((long)(t0 + r) * B_ + bz) * P_;
#pragma unroll
            for (int nt = 0; nt < 8; nt++) {
                const int gc = wn * 64 + nt * 8 + 2 * lanek;
                *(float2*)(g_attn + base + gc) =
                    make_float2(acco[mt][nt][2 * h] * inv, acco[mt][nt][2 * h + 1] * inv);
            }
        }
    }
}

// ---------------------------------------------------------------------------
extern "C" void kernel_launch(void* const* d_in, const int* in_sizes, int n_in,
                              void* d_out, int out_size)
{
    const float* query = (const float*)d_in[0];   // [T,B,D]
    const float* W_kqv = (const float*)d_in[1];   // [D, 3P]
    const float* b_kqv = (const float*)d_in[2];   // [3P]
    const float* W_out = (const float*)d_in[3];   // [P, O]
    const float* b_out = (const float*)d_in[4];   // [O]
    float* out = (float*)d_out;                   // [T,B,O]

    float *v, *vT, *at, *wkqvT, *woutT;
    cudaGetSymbolAddress((void**)&v,     g_v);
    cudaGetSymbolAddress((void**)&vT,    g_vT);
    cudaGetSymbolAddress((void**)&at,    g_attn);
    cudaGetSymbolAddress((void**)&wkqvT, g_wkqvT);
    cudaGetSymbolAddress((void**)&woutT, g_woutT);

    cudaFuncSetAttribute(gemm_mma<1>, cudaFuncAttributeMaxDynamicSharedMemorySize, SMG_BYTES);
    cudaFuncSetAttribute(gemm_mma<3>, cudaFuncAttributeMaxDynamicSharedMemorySize, SMG_BYTES);
    cudaFuncSetAttribute(flash_attn, cudaFuncAttributeMaxDynamicSharedMemorySize, SMF_BYTES);

    const long sQKV = (long)T_ * P_;
    const dim3 tb(32, 8);

    // 0) transpose weights to [N,K] K-major
    transpose_k<<<dim3(3 * P_ / 32, D_ / 32, 1), tb>>>(W_kqv, wkqvT, D_, 3 * P_, 0, 0);
    transpose_k<<<dim3(O_ / 32, P_ / 32, 1), tb>>>(W_out, woutT, P_, O_, 0, 0);

    // 1) QKV projection + split/scale/tf32-round/transpose
    gemm_mma<1><<<dim3(6, 256, 1), 256, SMG_BYTES>>>(
        query, wkqvT, nullptr, D_, D_, D_, 0, b_kqv);

    // 2) transpose v -> [B,P,T]
    transpose_k<<<dim3(P_ / 32, T_ / 32, B_), tb>>>(v, vT, T_, P_, sQKV, (long)P_ * T_);

    // 3) fused flash attention -> g_attn [T,B,P]
    flash_attn<<<dim3(T_ / QT, B_), 256, SMF_BYTES>>>();

    // 4) out = attn @ woutT^T + b_out
    gemm_mma<3><<<dim3(2, 256, 1), 256, SMG_BYTES>>>(
        at, woutT, out, P_, P_, P_, O_, b_out);
}

// round 5
// speedup vs baseline: 5.6108x; 1.8395x over previous
#include <cuda_runtime.h>
#include <cuda_fp16.h>
#include <cstdint>

// Problem dims (fixed by the dataset)
#define T_ 4096
#define B_ 8
#define D_ 256
#define P_ 256
#define O_ 256
#define SCALING 0.0625f   // P^-0.5 = 1/16
#define QT 64             // q rows per flash CTA
#define KT 128            // kv per flash tile
#define NTILE (T_ / KT)   // 32

// Scratch (device globals: allocation-free per harness rules)
__device__ __half g_q[(size_t)B_ * T_ * P_];       // [B,T,P] scaled q (fp16)
__device__ __half g_k[(size_t)B_ * T_ * P_];       // [B,T,P]
__device__ __half g_v[(size_t)B_ * T_ * P_];       // [B,T,P]
__device__ __half g_vT[(size_t)B_ * P_ * T_];      // [B,P,T]
__device__ float  g_attn[(size_t)T_ * B_ * P_];    // [T,B,P] fp32
__device__ __half g_wkqvT[(size_t)3 * P_ * D_];    // [3P, D]
__device__ __half g_woutT[(size_t)O_ * P_];        // [O, P]

// ---------------------------------------------------------------------------
__device__ __forceinline__ uint32_t f22h(float a, float b) {
    __half2 h = __floats2half2_rn(a, b);
    return *(uint32_t*)&h;
}
__device__ __forceinline__ void mma16(float* c, const uint32_t* a, uint32_t b0, uint32_t b1) {
    asm volatile(
        "mma.sync.aligned.m16n8k16.row.col.f32.f16.f16.f32 "
        "{%0,%1,%2,%3}, {%4,%5,%6,%7}, {%8,%9}, {%0,%1,%2,%3};"
        : "+f"(c[0]), "+f"(c[1]), "+f"(c[2]), "+f"(c[3])
        : "r"(a[0]), "r"(a[1]), "r"(a[2]), "r"(a[3]), "r"(b0), "r"(b1));
}
__device__ __forceinline__ void ldm4(uint32_t* r, uint32_t addr) {
    asm volatile("ldmatrix.sync.aligned.m8n8.x4.shared.b16 {%0,%1,%2,%3}, [%4];"
                 : "=r"(r[0]), "=r"(r[1]), "=r"(r[2]), "=r"(r[3]) : "r"(addr));
}
__device__ __forceinline__ uint32_t smem_u32(const void* p) {
    uint32_t a;
    asm("{ .reg .u64 t; cvta.to.shared.u64 t, %1; cvt.u32.u64 %0, t; }" : "=r"(a) : "l"(p));
    return a;
}
// address for ldmatrix.x4 inside a [rows][64 fp16] SW128-swizzled tile
__device__ __forceinline__ uint32_t ldm_addr(uint32_t tile, int rbase, int kk, int lane) {
    int row = rbase + (lane & 15);
    int c16 = kk * 2 + (lane >> 4);
    return tile + row * 128 + (uint32_t)((c16 * 16) ^ ((row & 7) * 16));
}
__device__ __forceinline__ void cpa16(uint32_t dst, const void* src) {
    asm volatile("cp.async.cg.shared.global [%0], [%1], 16;" :: "r"(dst), "l"(src));
}
#define CP_COMMIT() asm volatile("cp.async.commit_group;" ::: "memory")
#define CP_WAIT1()  asm volatile("cp.async.wait_group 1;" ::: "memory")
#define CP_WAIT0()  asm volatile("cp.async.wait_group 0;" ::: "memory")

// ---------------------------------------------------------------------------
// fp16 mma GEMM: CTA 128x128, K-chunk 64, double-buffered. A fp32 [M,K]
// (converted on the fly), B fp16 [N,K] K-major: D = A @ B^T (fp32 accum).
// 8 warps: wm=w&3 (4x32 m), wn=w>>2 (2x64 n).
// EPI: 1 = QKV split (+bias, q-scale, fp16 store to g_q/g_k/g_v)
//      3 = bias + fp32 C store
// ---------------------------------------------------------------------------
#define SMG_BYTES 65536   // A 2x16KB | B 2x16KB

template<int EPI>
__global__ void __launch_bounds__(256)
gemm_h(const float* __restrict__ A, const __half* __restrict__ Bm,
       float* __restrict__ C, int K, int lda, int ldb, int ldc,
       const float* __restrict__ bias)
{
    extern __shared__ char smem[];
    const uint32_t sb = smem_u32(smem);
    const int tid = threadIdx.x;
    const int w = tid >> 5, lane = tid & 31;
    const int wm = w & 3, wn = w >> 2;
    const int lane4 = lane >> 2, lanek = lane & 3;
    const int m0 = blockIdx.y * 128, n0 = blockIdx.x * 128;

    A  += (long)m0 * lda;
    Bm += (long)n0 * ldb;

    float acc[16][4];
#pragma unroll
    for (int i = 0; i < 16; i++)
#pragma unroll
        for (int j = 0; j < 4; j++) acc[i][j] = 0.f;

    float4 pa[8], pb[4];
    const int NC = K / 64;
#pragma unroll
    for (int i = 0; i < 4; i++) {
        int f = tid + i * 256, r = f >> 3, c16 = f & 7;
        pa[2*i]   = *(const float4*)(A + (long)r * lda + c16 * 8);
        pa[2*i+1] = *(const float4*)(A + (long)r * lda + c16 * 8 + 4);
        pb[i]     = *(const float4*)(Bm + (long)r * ldb + c16 * 8);
    }

    for (int c = 0; c < NC; ++c) {
        const int s = c & 1;
        const uint32_t aS = sb + s * 16384;
        const uint32_t bS = sb + 32768 + s * 16384;
#pragma unroll
        for (int i = 0; i < 4; i++) {
            int f = tid + i * 256, r = f >> 3, c16 = f & 7;
            uint32_t off = (uint32_t)(r * 128 + ((c16 * 16) ^ ((r & 7) * 16)));
            uint32_t h0 = f22h(pa[2*i].x,   pa[2*i].y);
            uint32_t h1 = f22h(pa[2*i].z,   pa[2*i].w);
            uint32_t h2 = f22h(pa[2*i+1].x, pa[2*i+1].y);
            uint32_t h3 = f22h(pa[2*i+1].z, pa[2*i+1].w);
            asm volatile("st.shared.v4.b32 [%0], {%1,%2,%3,%4};"
                         :: "r"(aS + off), "r"(h0), "r"(h1), "r"(h2), "r"(h3));
            const uint32_t* pbu = (const uint32_t*)&pb[i];
            asm volatile("st.shared.v4.b32 [%0], {%1,%2,%3,%4};"
                         :: "r"(bS + off), "r"(pbu[0]), "r"(pbu[1]), "r"(pbu[2]), "r"(pbu[3]));
        }
        __syncthreads();
        if (c + 1 < NC) {
            const float*  Ag = A  + (c + 1) * 64;
            const __half* Bg = Bm + (c + 1) * 64;
#pragma unroll
            for (int i = 0; i < 4; i++) {
                int f = tid + i * 256, r = f >> 3, c16 = f & 7;
                pa[2*i]   = *(const float4*)(Ag + (long)r * lda + c16 * 8);
                pa[2*i+1] = *(const float4*)(Ag + (long)r * lda + c16 * 8 + 4);
                pb[i]     = *(const float4*)(Bg + (long)r * ldb + c16 * 8);
            }
        }
#pragma unroll
        for (int kk = 0; kk < 4; ++kk) {
            uint32_t af[2][4], bf[4][4];
#pragma unroll
            for (int mt = 0; mt < 2; ++mt)
                ldm4(af[mt], ldm_addr(aS, wm * 32 + mt * 16, kk, lane));
#pragma unroll
            for (int nb = 0; nb < 4; ++nb)
                ldm4(bf[nb], ldm_addr(bS, wn * 64 + nb * 16, kk, lane));
#pragma unroll
            for (int mt = 0; mt < 2; ++mt)
#pragma unroll
                for (int n8 = 0; n8 < 8; ++n8)
                    mma16(acc[mt * 8 + n8], af[mt],
                          bf[n8 >> 1][n8 & 1], bf[n8 >> 1][2 + (n8 & 1)]);
        }
        __syncthreads();
    }

    const int rb = m0 + wm * 32 + lane4;
    const int cb = n0 + wn * 64 + 2 * lanek;
#pragma unroll
    for (int mt = 0; mt < 2; ++mt) {
        const int r = rb + mt * 16;
#pragma unroll
        for (int n8 = 0; n8 < 8; ++n8) {
            float* a4 = acc[mt * 8 + n8];
            const int gc = cb + n8 * 8;
            if (EPI == 1) {
                const int seg = gc >> 8, col = gc & 255;
                float2 bv = *(const float2*)(bias + gc);
                const float scl = (seg == 0) ? SCALING : 1.0f;
                __half* dstb = (seg == 0 ? g_q : (seg == 1 ? g_k : g_v));
                int t0 = r >> 3, b0 = r & 7;
                *(uint32_t*)(dstb + ((long)b0 * T_ + t0) * P_ + col) =
                    f22h((a4[0] + bv.x) * scl, (a4[1] + bv.y) * scl);
                int t1 = (r + 8) >> 3, b1 = (r + 8) & 7;
                *(uint32_t*)(dstb + ((long)b1 * T_ + t1) * P_ + col) =
                    f22h((a4[2] + bv.x) * scl, (a4[3] + bv.y) * scl);
            } else {
                float2 bv = *(const float2*)(bias + gc);
                *(float2*)(C + (long)r * ldc + gc) =
                    make_float2(a4[0] + bv.x, a4[1] + bv.y);
                *(float2*)(C + (long)(r + 8) * ldc + gc) =
                    make_float2(a4[2] + bv.x, a4[3] + bv.y);
            }
        }
    }
}

// ---------------------------------------------------------------------------
// Batched 32x32 tiled transpose with dtype convert
// ---------------------------------------------------------------------------
template<typename S, typename D>
__global__ void __launch_bounds__(256)
transpose_t(const S* __restrict__ src, D* __restrict__ dst,
            int R, int C, long sS, long sD)
{
    __shared__ float tile[32][33];
    src += (long)blockIdx.z * sS;
    dst += (long)blockIdx.z * sD;
    const int c0 = blockIdx.x * 32, r0 = blockIdx.y * 32;
    const int x = threadIdx.x, y = threadIdx.y;
#pragma unroll
    for (int i = 0; i < 32; i += 8)
        tile[y + i][x] = (float)src[(long)(r0 + y + i) * C + c0 + x];
    __syncthreads();
#pragma unroll
    for (int i = 0; i < 32; i += 8)
        dst[(long)(c0 + y + i) * R + r0 + x] = (D)tile[x][y + i];
}

// ---------------------------------------------------------------------------
// Flash attention fp16: per CTA = 64 q rows x one batch, kv tiles of 128.
// smem: Q 32KB (4 chunks [64][64]) | K 3x16KB | V 2x32KB | P 16KB | stats.
// S warps: wm=w&1 (2x32 rows), wn=w>>1 (4x32 kv). PV: wn covers 4x64 d-cols.
// ---------------------------------------------------------------------------
#define SM_Q    0
#define SM_K    32768
#define SM_V    (SM_K + 3 * 16384)
#define SM_P    (SM_V + 2 * 32768)
#define SM_ST   (SM_P + 16384)
#define SMF_BYTES (SM_ST + 2816)
// stats: pmax[4][64] @+0, psum[4][64] @+1024, m[64] @+2048, l[64] @+2304,
//        scale[64] @+2560

__global__ void __launch_bounds__(256, 1)
flash_attn()
{
    extern __shared__ char smem[];
    const uint32_t sb = smem_u32(smem);
    const int tid = threadIdx.x;
    const int w = tid >> 5, lane = tid & 31;
    const int wm = w & 1, wn = w >> 1;
    const int lane4 = lane >> 2, lanek = lane & 3;
    const int bz = blockIdx.y;
    const int t0 = blockIdx.x * QT;

    const __half* qb  = g_q  + ((long)bz * T_ + t0) * P_;
    const __half* kb  = g_k  + (long)bz * T_ * P_;
    const __half* vtb = g_vT + (long)bz * P_ * T_;

    float* pmax  = (float*)(smem + SM_ST);
    float* psum  = (float*)(smem + SM_ST + 1024);
    float* m_st  = (float*)(smem + SM_ST + 2048);
    float* l_st  = (float*)(smem + SM_ST + 2304);
    float* sc_st = (float*)(smem + SM_ST + 2560);

    // ---- Q resident: 4 k-chunks of [64][64] fp16, SW128 swizzle
#pragma unroll
    for (int i = 0; i < 8; i++) {
        int f = tid + i * 256;          // 0..2047 16B units
        int r = f >> 5, c32 = f & 31;   // row, 16B col of 256-half row
        int kc = c32 >> 3, c16 = c32 & 7;
        float4 v = *(const float4*)(qb + (long)r * P_ + c32 * 8);
        uint32_t off = (uint32_t)(kc * 8192 + r * 128 + ((c16 * 16) ^ ((r & 7) * 16)));
        *(float4*)(smem + SM_Q + off) = v;
    }
    if (tid < QT) { m_st[tid] = -3.4e38f; l_st[tid] = 0.f; }

    float acco[2][8][4];
#pragma unroll
    for (int mt = 0; mt < 2; mt++)
#pragma unroll
        for (int n8 = 0; n8 < 8; n8++)
#pragma unroll
            for (int e = 0; e < 4; e++) acco[mt][n8][e] = 0.f;

    // prologue: K tile0 chunks 0,1 (bufs 0,1)
#pragma unroll
    for (int pc = 0; pc < 2; pc++) {
#pragma unroll
        for (int i = 0; i < 4; i++) {
            int f = tid + i * 256, r = f >> 3, c16 = f & 7;
            uint32_t dst = sb + SM_K + pc * 16384 +
                           (uint32_t)(r * 128 + ((c16 * 16) ^ ((r & 7) * 16)));
            cpa16(dst, kb + (long)r * P_ + pc * 64 + c16 * 8);
        }
        CP_COMMIT();
    }

    for (int j = 0; j < NTILE; ++j) {
        // ============== S phase: S[64x128] = Q @ Kj^T  (4 chunks) ==========
        float accs[2][4][4];
#pragma unroll
        for (int mt = 0; mt < 2; mt++)
#pragma unroll
            for (int nt = 0; nt < 4; nt++)
#pragma unroll
                for (int e = 0; e < 4; e++) accs[mt][nt][e] = 0.f;

        for (int c = 0; c < 4; ++c) {
            CP_WAIT1();
            __syncthreads();
            // issue one group: K chunks c+2 of this tile, or V chunks 0/1
            if (c < 2) {
                const int kg = j * 4 + c + 2;
#pragma unroll
                for (int i = 0; i < 4; i++) {
                    int f = tid + i * 256, r = f >> 3, c16 = f & 7;
                    uint32_t dst = sb + SM_K + (kg % 3) * 16384 +
                                   (uint32_t)(r * 128 + ((c16 * 16) ^ ((r & 7) * 16)));
                    cpa16(dst, kb + (long)(j * KT + r) * P_ + (c + 2) * 64 + c16 * 8);
                }
            } else {
                const int d = c - 2;   // V chunk 0/1 -> Vbuf 0/1
#pragma unroll
                for (int i = 0; i < 8; i++) {
                    int f = tid + i * 256, r = f >> 3, c16 = f & 7;  // r: d-row 0..255
                    uint32_t dst = sb + SM_V + d * 32768 +
                                   (uint32_t)(r * 128 + ((c16 * 16) ^ ((r & 7) * 16)));
                    cpa16(dst, vtb + (long)r * T_ + j * KT + d * 64 + c16 * 8);
                }
            }
            CP_COMMIT();

            const uint32_t aT = sb + SM_Q + c * 8192;
            const uint32_t bT = sb + SM_K + ((j * 4 + c) % 3) * 16384;
#pragma unroll
            for (int kk = 0; kk < 4; ++kk) {
                uint32_t af[2][4], bf[2][4];
#pragma unroll
                for (int mt = 0; mt < 2; ++mt)
                    ldm4(af[mt], ldm_addr(aT, wm * 32 + mt * 16, kk, lane));
#pragma unroll
                for (int nb = 0; nb < 2; ++nb)
                    ldm4(bf[nb], ldm_addr(bT, wn * 32 + nb * 16, kk, lane));
#pragma unroll
                for (int mt = 0; mt < 2; ++mt)
#pragma unroll
                    for (int n8 = 0; n8 < 4; ++n8)
                        mma16(accs[mt][n8], af[mt],
                              bf[n8 >> 1][n8 & 1], bf[n8 >> 1][2 + (n8 & 1)]);
            }
        }

        // ============== online softmax =====================================
#pragma unroll
        for (int mt = 0; mt < 2; mt++) {
#pragma unroll
            for (int h = 0; h < 2; h++) {
                float mx = -3.4e38f;
#pragma unroll
                for (int nt = 0; nt < 4; nt++)
                    mx = fmaxf(mx, fmaxf(accs[mt][nt][2 * h], accs[mt][nt][2 * h + 1]));
                mx = fmaxf(mx, __shfl_xor_sync(0xffffffffu, mx, 1));
                mx = fmaxf(mx, __shfl_xor_sync(0xffffffffu, mx, 2));
                if (lanek == 0)
                    pmax[wn * 64 + wm * 32 + mt * 16 + lane4 + 8 * h] = mx;
            }
        }
        __syncthreads();
        if (tid < QT) {
            float mo = m_st[tid];
            float mn = fmaxf(fmaxf(pmax[tid], pmax[64 + tid]),
                             fmaxf(pmax[128 + tid], pmax[192 + tid]));
            mn = fmaxf(mo, mn);
            m_st[tid] = mn;
            sc_st[tid] = __expf(mo - mn);
        }
        __syncthreads();

#pragma unroll
        for (int mt = 0; mt < 2; mt++) {
#pragma unroll
            for (int h = 0; h < 2; h++) {
                const int r = wm * 32 + mt * 16 + lane4 + 8 * h;
                const float m = m_st[r];
                float s = 0.f;
#pragma unroll
                for (int nt = 0; nt < 4; nt++) {
                    float e0 = __expf(accs[mt][nt][2 * h] - m);
                    float e1 = __expf(accs[mt][nt][2 * h + 1] - m);
                    s += e0 + e1;
                    const int cg = wn * 32 + nt * 8 + 2 * lanek;  // kv col 0..127
                    const int kc = cg >> 6, cw = cg & 63;
                    uint32_t off = (uint32_t)(kc * 8192 + r * 128 +
                                   (((cw >> 3) * 16) ^ ((r & 7) * 16)) + (cw & 7) * 2);
                    *(uint32_t*)(smem + SM_P + off) = f22h(e0, e1);
                }
                s += __shfl_xor_sync(0xffffffffu, s, 1);
                s += __shfl_xor_sync(0xffffffffu, s, 2);
                if (lanek == 0) psum[wn * 64 + r] = s;
                const float scl = sc_st[r];
#pragma unroll
                for (int n8 = 0; n8 < 8; n8++) {
                    acco[mt][n8][2 * h]     *= scl;
                    acco[mt][n8][2 * h + 1] *= scl;
                }
            }
        }
        __syncthreads();
        if (tid < QT)
            l_st[tid] = l_st[tid] * sc_st[tid] +
                        (psum[tid] + psum[64 + tid] + psum[128 + tid] + psum[192 + tid]);

        // ============== PV phase: O += P @ Vj  (2 chunks over kv) ==========
        for (int d = 0; d < 2; ++d) {
            CP_WAIT1();
            __syncthreads();
            // issue one group: K chunks 0/1 of next tile
            {
                const int jn = (j + 1) & (NTILE - 1);
                const int kg = (j + 1) * 4 + d;
#pragma unroll
                for (int i = 0; i < 4; i++) {
                    int f = tid + i * 256, r = f >> 3, c16 = f & 7;
                    uint32_t dst = sb + SM_K + (kg % 3) * 16384 +
                                   (uint32_t)(r * 128 + ((c16 * 16) ^ ((r & 7) * 16)));
                    cpa16(dst, kb + (long)(jn * KT + r) * P_ + d * 64 + c16 * 8);
                }
                CP_COMMIT();
            }
            const uint32_t aT = sb + SM_P + d * 8192;
            const uint32_t bT = sb + SM_V + d * 32768;
#pragma unroll
            for (int kk = 0; kk < 4; ++kk) {
                uint32_t af[2][4], bf[4][4];
#pragma unroll
                for (int mt = 0; mt < 2; ++mt)
                    ldm4(af[mt], ldm_addr(aT, wm * 32 + mt * 16, kk, lane));
#pragma unroll
                for (int nb = 0; nb < 4; ++nb)
                    ldm4(bf[nb], ldm_addr(bT, wn * 64 + nb * 16, kk, lane));
#pragma unroll
                for (int mt = 0; mt < 2; ++mt)
#pragma unroll
                    for (int n8 = 0; n8 < 8; ++n8)
                        mma16(acco[mt][n8], af[mt],
                              bf[n8 >> 1][n8 & 1], bf[n8 >> 1][2 + (n8 & 1)]);
            }
        }
    }

    CP_WAIT0();
    __syncthreads();

    // ---- epilogue: O / l -> g_attn [T,B,P] fp32
#pragma unroll
    for (int mt = 0; mt < 2; mt++) {
#pragma unroll
        for (int h = 0; h < 2; h++) {
            const int r = wm * 32 + mt * 16 + lane4 + 8 * h;
            const float inv = 1.0f / l_st[r];
            const long base = ((long)(t0 + r) * B_ + bz) * P_;
#pragma unroll
            for (int n8 = 0; n8 < 8; n8++) {
                const int gc = wn * 64 + n8 * 8 + 2 * lanek;
                *(float2*)(g_attn + base + gc) =
                    make_float2(acco[mt][n8][2 * h] * inv, acco[mt][n8][2 * h + 1] * inv);
            }
        }
    }
}

// ---------------------------------------------------------------------------
extern "C" void kernel_launch(void* const* d_in, const int* in_sizes, int n_in,
                              void* d_out, int out_size)
{
    const float* query = (const float*)d_in[0];   // [T,B,D]
    const float* W_kqv = (const float*)d_in[1];   // [D, 3P]
    const float* b_kqv = (const float*)d_in[2];   // [3P]
    const float* W_out = (const float*)d_in[3];   // [P, O]
    const float* b_out = (const float*)d_in[4];   // [O]
    float* out = (float*)d_out;                   // [T,B,O]

    __half *v, *vT, *wkqvT, *woutT;
    float *at;
    cudaGetSymbolAddress((void**)&v,     g_v);
    cudaGetSymbolAddress((void**)&vT,    g_vT);
    cudaGetSymbolAddress((void**)&at,    g_attn);
    cudaGetSymbolAddress((void**)&wkqvT, g_wkqvT);
    cudaGetSymbolAddress((void**)&woutT, g_woutT);

    cudaFuncSetAttribute(gemm_h<1>, cudaFuncAttributeMaxDynamicSharedMemorySize, SMG_BYTES);
    cudaFuncSetAttribute(gemm_h<3>, cudaFuncAttributeMaxDynamicSharedMemorySize, SMG_BYTES);
    cudaFuncSetAttribute(flash_attn, cudaFuncAttributeMaxDynamicSharedMemorySize, SMF_BYTES);

    const long sQKV = (long)T_ * P_;
    const dim3 tb(32, 8);

    // 0) weights -> [N,K] K-major fp16
    transpose_t<float, __half><<<dim3(3 * P_ / 32, D_ / 32, 1), tb>>>(W_kqv, wkqvT, D_, 3 * P_, 0, 0);
    transpose_t<float, __half><<<dim3(O_ / 32, P_ / 32, 1), tb>>>(W_out, woutT, P_, O_, 0, 0);

    // 1) QKV projection + split/scale -> g_q/g_k/g_v fp16
    gemm_h<1><<<dim3(6, 256, 1), 256, SMG_BYTES>>>(
        query, wkqvT, nullptr, D_, D_, D_, 0, b_kqv);

    // 2) v -> vT [B,P,T] fp16
    transpose_t<__half, __half><<<dim3(P_ / 32, T_ / 32, B_), tb>>>(v, vT, T_, P_, sQKV, (long)P_ * T_);

    // 3) fused flash attention -> g_attn [T,B,P] fp32
    flash_attn<<<dim3(T_ / QT, B_), 256, SMF_BYTES>>>();

    // 4) out = attn @ woutT^T + b_out
    gemm_h<3><<<dim3(2, 256, 1), 256, SMG_BYTES>>>(
        at, woutT, out, P_, P_, P_, O_, b_out);
}

// round 6
// speedup vs baseline: 6.0202x; 1.0730x over previous
#include <cuda_runtime.h>
#include <cuda_fp16.h>
#include <cstdint>

// Problem dims (fixed by the dataset)
#define T_ 4096
#define B_ 8
#define D_ 256
#define P_ 256
#define O_ 256
#define SCALING 0.0625f   // P^-0.5 = 1/16
#define QT 64             // q rows per flash CTA
#define KT2 256           // kv per flash tile
#define NT2 (T_ / KT2)    // 16

// Scratch (device globals: allocation-free per harness rules)
__device__ __half g_q[(size_t)B_ * T_ * P_];       // [B,T,P] scaled q (fp16)
__device__ __half g_k[(size_t)B_ * T_ * P_];       // [B,T,P]
__device__ __half g_v[(size_t)B_ * T_ * P_];       // [B,T,P]
__device__ __half g_vT[(size_t)B_ * P_ * T_];      // [B,P,T]
__device__ float  g_attn[(size_t)T_ * B_ * P_];    // [T,B,P] fp32
__device__ __half g_wkqvT[(size_t)3 * P_ * D_];    // [3P, D]
__device__ __half g_woutT[(size_t)O_ * P_];        // [O, P]

// ---------------------------------------------------------------------------
__device__ __forceinline__ uint32_t f22h(float a, float b) {
    __half2 h = __floats2half2_rn(a, b);
    return *(uint32_t*)&h;
}
__device__ __forceinline__ void mma16(float* c, const uint32_t* a, uint32_t b0, uint32_t b1) {
    asm volatile(
        "mma.sync.aligned.m16n8k16.row.col.f32.f16.f16.f32 "
        "{%0,%1,%2,%3}, {%4,%5,%6,%7}, {%8,%9}, {%0,%1,%2,%3};"
        : "+f"(c[0]), "+f"(c[1]), "+f"(c[2]), "+f"(c[3])
        : "r"(a[0]), "r"(a[1]), "r"(a[2]), "r"(a[3]), "r"(b0), "r"(b1));
}
__device__ __forceinline__ void ldm4(uint32_t* r, uint32_t addr) {
    asm volatile("ldmatrix.sync.aligned.m8n8.x4.shared.b16 {%0,%1,%2,%3}, [%4];"
                 : "=r"(r[0]), "=r"(r[1]), "=r"(r[2]), "=r"(r[3]) : "r"(addr));
}
__device__ __forceinline__ uint32_t smem_u32(const void* p) {
    uint32_t a;
    asm("{ .reg .u64 t; cvta.to.shared.u64 t, %1; cvt.u32.u64 %0, t; }" : "=r"(a) : "l"(p));
    return a;
}
// address for ldmatrix.x4 inside a [rows][64 fp16] SW128-swizzled tile
__device__ __forceinline__ uint32_t ldm_addr(uint32_t tile, int rbase, int kk, int lane) {
    int row = rbase + (lane & 15);
    int c16 = kk * 2 + (lane >> 4);
    return tile + row * 128 + (uint32_t)((c16 * 16) ^ ((row & 7) * 16));
}
__device__ __forceinline__ void cpa16(uint32_t dst, const void* src) {
    asm volatile("cp.async.cg.shared.global [%0], [%1], 16;" :: "r"(dst), "l"(src));
}
#define CP_COMMIT() asm volatile("cp.async.commit_group;" ::: "memory")
#define CP_WAIT1()  asm volatile("cp.async.wait_group 1;" ::: "memory")
#define CP_WAIT0()  asm volatile("cp.async.wait_group 0;" ::: "memory")

// ---------------------------------------------------------------------------
// fp16 mma GEMM (unchanged from R5): CTA 128x128, K-chunk 64, double-buffered.
// EPI: 1 = QKV split, 3 = bias + fp32 C store
// ---------------------------------------------------------------------------
#define SMG_BYTES 65536

template<int EPI>
__global__ void __launch_bounds__(256)
gemm_h(const float* __restrict__ A, const __half* __restrict__ Bm,
       float* __restrict__ C, int K, int lda, int ldb, int ldc,
       const float* __restrict__ bias)
{
    extern __shared__ char smem[];
    const uint32_t sb = smem_u32(smem);
    const int tid = threadIdx.x;
    const int w = tid >> 5, lane = tid & 31;
    const int wm = w & 3, wn = w >> 2;
    const int lane4 = lane >> 2, lanek = lane & 3;
    const int m0 = blockIdx.y * 128, n0 = blockIdx.x * 128;

    A  += (long)m0 * lda;
    Bm += (long)n0 * ldb;

    float acc[16][4];
#pragma unroll
    for (int i = 0; i < 16; i++)
#pragma unroll
        for (int j = 0; j < 4; j++) acc[i][j] = 0.f;

    float4 pa[8], pb[4];
    const int NC = K / 64;
#pragma unroll
    for (int i = 0; i < 4; i++) {
        int f = tid + i * 256, r = f >> 3, c16 = f & 7;
        pa[2*i]   = *(const float4*)(A + (long)r * lda + c16 * 8);
        pa[2*i+1] = *(const float4*)(A + (long)r * lda + c16 * 8 + 4);
        pb[i]     = *(const float4*)(Bm + (long)r * ldb + c16 * 8);
    }

    for (int c = 0; c < NC; ++c) {
        const int s = c & 1;
        const uint32_t aS = sb + s * 16384;
        const uint32_t bS = sb + 32768 + s * 16384;
#pragma unroll
        for (int i = 0; i < 4; i++) {
            int f = tid + i * 256, r = f >> 3, c16 = f & 7;
            uint32_t off = (uint32_t)(r * 128 + ((c16 * 16) ^ ((r & 7) * 16)));
            uint32_t h0 = f22h(pa[2*i].x,   pa[2*i].y);
            uint32_t h1 = f22h(pa[2*i].z,   pa[2*i].w);
            uint32_t h2 = f22h(pa[2*i+1].x, pa[2*i+1].y);
            uint32_t h3 = f22h(pa[2*i+1].z, pa[2*i+1].w);
            asm volatile("st.shared.v4.b32 [%0], {%1,%2,%3,%4};"
                         :: "r"(aS + off), "r"(h0), "r"(h1), "r"(h2), "r"(h3));
            const uint32_t* pbu = (const uint32_t*)&pb[i];
            asm volatile("st.shared.v4.b32 [%0], {%1,%2,%3,%4};"
                         :: "r"(bS + off), "r"(pbu[0]), "r"(pbu[1]), "r"(pbu[2]), "r"(pbu[3]));
        }
        __syncthreads();
        if (c + 1 < NC) {
            const float*  Ag = A  + (c + 1) * 64;
            const __half* Bg = Bm + (c + 1) * 64;
#pragma unroll
            for (int i = 0; i < 4; i++) {
                int f = tid + i * 256, r = f >> 3, c16 = f & 7;
                pa[2*i]   = *(const float4*)(Ag + (long)r * lda + c16 * 8);
                pa[2*i+1] = *(const float4*)(Ag + (long)r * lda + c16 * 8 + 4);
                pb[i]     = *(const float4*)(Bg + (long)r * ldb + c16 * 8);
            }
        }
#pragma unroll
        for (int kk = 0; kk < 4; ++kk) {
            uint32_t af[2][4], bf[4][4];
#pragma unroll
            for (int mt = 0; mt < 2; ++mt)
                ldm4(af[mt], ldm_addr(aS, wm * 32 + mt * 16, kk, lane));
#pragma unroll
            for (int nb = 0; nb < 4; ++nb)
                ldm4(bf[nb], ldm_addr(bS, wn * 64 + nb * 16, kk, lane));
#pragma unroll
            for (int mt = 0; mt < 2; ++mt)
#pragma unroll
                for (int n8 = 0; n8 < 8; ++n8)
                    mma16(acc[mt * 8 + n8], af[mt],
                          bf[n8 >> 1][n8 & 1], bf[n8 >> 1][2 + (n8 & 1)]);
        }
        __syncthreads();
    }

    const int rb = m0 + wm * 32 + lane4;
    const int cb = n0 + wn * 64 + 2 * lanek;
#pragma unroll
    for (int mt = 0; mt < 2; ++mt) {
        const int r = rb + mt * 16;
#pragma unroll
        for (int n8 = 0; n8 < 8; ++n8) {
            float* a4 = acc[mt * 8 + n8];
            const int gc = cb + n8 * 8;
            if (EPI == 1) {
                const int seg = gc >> 8, col = gc & 255;
                float2 bv = *(const float2*)(bias + gc);
                const float scl = (seg == 0) ? SCALING : 1.0f;
                __half* dstb = (seg == 0 ? g_q : (seg == 1 ? g_k : g_v));
                int t0 = r >> 3, b0 = r & 7;
                *(uint32_t*)(dstb + ((long)b0 * T_ + t0) * P_ + col) =
                    f22h((a4[0] + bv.x) * scl, (a4[1] + bv.y) * scl);
                int t1 = (r + 8) >> 3, b1 = (r + 8) & 7;
                *(uint32_t*)(dstb + ((long)b1 * T_ + t1) * P_ + col) =
                    f22h((a4[2] + bv.x) * scl, (a4[3] + bv.y) * scl);
            } else {
                float2 bv = *(const float2*)(bias + gc);
                *(float2*)(C + (long)r * ldc + gc) =
                    make_float2(a4[0] + bv.x, a4[1] + bv.y);
                *(float2*)(C + (long)(r + 8) * ldc + gc) =
                    make_float2(a4[2] + bv.x, a4[3] + bv.y);
            }
        }
    }
}

// ---------------------------------------------------------------------------
// Batched 32x32 tiled transpose with dtype convert
// ---------------------------------------------------------------------------
template<typename S, typename D>
__global__ void __launch_bounds__(256)
transpose_t(const S* __restrict__ src, D* __restrict__ dst,
            int R, int C, long sS, long sD)
{
    __shared__ float tile[32][33];
    src += (long)blockIdx.z * sS;
    dst += (long)blockIdx.z * sD;
    const int c0 = blockIdx.x * 32, r0 = blockIdx.y * 32;
    const int x = threadIdx.x, y = threadIdx.y;
#pragma unroll
    for (int i = 0; i < 32; i += 8)
        tile[y + i][x] = (float)src[(long)(r0 + y + i) * C + c0 + x];
    __syncthreads();
#pragma unroll
    for (int i = 0; i < 32; i += 8)
        dst[(long)(c0 + y + i) * R + r0 + x] = (D)tile[x][y + i];
}

// ---------------------------------------------------------------------------
// Flash attention fp16, 512 threads (16 warps), kv tiles of 256.
// smem: Q 32K (4x[64][64]) | K 2x32K ([256kv][64d] chunks) | V 2x32K
// ([256d][64kv] chunks) | P 32K (4x[64][64]) | stats.
// Warp layout (both phases): wm=w&1 (2x32 rows), wn=w>>1 (8x32 cols).
// ---------------------------------------------------------------------------
#define SM_Q    0
#define SM_K    32768
#define SM_V    (SM_K + 2 * 32768)
#define SM_P    (SM_V + 2 * 32768)
#define SM_ST   (SM_P + 32768)
#define SMF_BYTES (SM_ST + 5120)
// stats: pmax[8][64] @+0, psum[8][64] @+2048, m[64] @+4096, l[64] @+4352,
//        scale[64] @+4608

__global__ void __launch_bounds__(512, 1)
flash_attn()
{
    extern __shared__ char smem[];
    const uint32_t sb = smem_u32(smem);
    const int tid = threadIdx.x;
    const int w = tid >> 5, lane = tid & 31;
    const int wm = w & 1, wn = w >> 1;      // wn 0..7
    const int lane4 = lane >> 2, lanek = lane & 3;
    const int bz = blockIdx.y;
    const int t0 = blockIdx.x * QT;

    const __half* qb  = g_q  + ((long)bz * T_ + t0) * P_;
    const __half* kb  = g_k  + (long)bz * T_ * P_;
    const __half* vtb = g_vT + (long)bz * P_ * T_;

    float* pmax  = (float*)(smem + SM_ST);
    float* psum  = (float*)(smem + SM_ST + 2048);
    float* m_st  = (float*)(smem + SM_ST + 4096);
    float* l_st  = (float*)(smem + SM_ST + 4352);
    float* sc_st = (float*)(smem + SM_ST + 4608);

    // ---- Q resident: 4 d-chunks of [64][64] fp16, SW128 swizzle
#pragma unroll
    for (int i = 0; i < 4; i++) {
        int f = tid + i * 512;          // 0..2047 16B units
        int r = f >> 5, c32 = f & 31;
        int kc = c32 >> 3, c16 = c32 & 7;
        float4 v = *(const float4*)(qb + (long)r * P_ + c32 * 8);
        uint32_t off = (uint32_t)(kc * 8192 + r * 128 + ((c16 * 16) ^ ((r & 7) * 16)));
        *(float4*)(smem + SM_Q + off) = v;
    }
    if (tid < QT) { m_st[tid] = -3.4e38f; l_st[tid] = 0.f; }

    float acco[2][4][4];
#pragma unroll
    for (int mt = 0; mt < 2; mt++)
#pragma unroll
        for (int nt = 0; nt < 4; nt++)
#pragma unroll
            for (int e = 0; e < 4; e++) acco[mt][nt][e] = 0.f;

    // prologue: K tile0 d-chunks 0,1 into kbuf 0,1
#pragma unroll
    for (int pc = 0; pc < 2; pc++) {
#pragma unroll
        for (int i = 0; i < 4; i++) {
            int f = tid + i * 512, r = f >> 3, c16 = f & 7;   // r: kv row 0..255
            uint32_t dst = sb + SM_K + pc * 32768 +
                           (uint32_t)(r * 128 + ((c16 * 16) ^ ((r & 7) * 16)));
            cpa16(dst, kb + (long)r * P_ + pc * 64 + c16 * 8);
        }
        CP_COMMIT();
    }

    for (int j = 0; j < NT2; ++j) {
        // ============== S phase: S[64x256] = Q @ Kj^T  (4 d-chunks) ========
        float accs[2][4][4];
#pragma unroll
        for (int mt = 0; mt < 2; mt++)
#pragma unroll
            for (int nt = 0; nt < 4; nt++)
#pragma unroll
                for (int e = 0; e < 4; e++) accs[mt][nt][e] = 0.f;

        for (int c = 0; c < 4; ++c) {
            CP_WAIT1();
            __syncthreads();
            const uint32_t aT = sb + SM_Q + c * 8192;
            const uint32_t bT = sb + SM_K + (c & 1) * 32768;
#pragma unroll
            for (int kk = 0; kk < 4; ++kk) {
                uint32_t af[2][4], bf[2][4];
#pragma unroll
                for (int mt = 0; mt < 2; ++mt)
                    ldm4(af[mt], ldm_addr(aT, wm * 32 + mt * 16, kk, lane));
#pragma unroll
                for (int nb = 0; nb < 2; ++nb)
                    ldm4(bf[nb], ldm_addr(bT, wn * 32 + nb * 16, kk, lane));
#pragma unroll
                for (int mt = 0; mt < 2; ++mt)
#pragma unroll
                    for (int n8 = 0; n8 < 4; ++n8)
                        mma16(accs[mt][n8], af[mt],
                              bf[n8 >> 1][n8 & 1], bf[n8 >> 1][2 + (n8 & 1)]);
            }
            __syncthreads();
            // issue next group (after sync: WAR-safe to reuse buffers)
            if (c < 2) {
                // K d-chunk c+2 of this tile -> kbuf (c&1)
#pragma unroll
                for (int i = 0; i < 4; i++) {
                    int f = tid + i * 512, r = f >> 3, c16 = f & 7;
                    uint32_t dst = sb + SM_K + (c & 1) * 32768 +
                                   (uint32_t)(r * 128 + ((c16 * 16) ^ ((r & 7) * 16)));
                    cpa16(dst, kb + (long)(j * KT2 + r) * P_ + (c + 2) * 64 + c16 * 8);
                }
            } else {
                // V kv-chunk c-2 -> vbuf (c-2)
                const int vc = c - 2;
#pragma unroll
                for (int i = 0; i < 4; i++) {
                    int f = tid + i * 512, r = f >> 3, c16 = f & 7;  // r: d row 0..255
                    uint32_t dst = sb + SM_V + vc * 32768 +
                                   (uint32_t)(r * 128 + ((c16 * 16) ^ ((r & 7) * 16)));
                    cpa16(dst, vtb + (long)r * T_ + j * KT2 + vc * 64 + c16 * 8);
                }
            }
            CP_COMMIT();
        }

        // ============== online softmax over 256 kv cols ====================
#pragma unroll
        for (int mt = 0; mt < 2; mt++) {
#pragma unroll
            for (int h = 0; h < 2; h++) {
                float mx = -3.4e38f;
#pragma unroll
                for (int nt = 0; nt < 4; nt++)
                    mx = fmaxf(mx, fmaxf(accs[mt][nt][2 * h], accs[mt][nt][2 * h + 1]));
                mx = fmaxf(mx, __shfl_xor_sync(0xffffffffu, mx, 1));
                mx = fmaxf(mx, __shfl_xor_sync(0xffffffffu, mx, 2));
                if (lanek == 0)
                    pmax[wn * 64 + wm * 32 + mt * 16 + lane4 + 8 * h] = mx;
            }
        }
        __syncthreads();
        if (tid < QT) {
            float mo = m_st[tid];
            float mn = mo;
#pragma unroll
            for (int g = 0; g < 8; g++) mn = fmaxf(mn, pmax[g * 64 + tid]);
            m_st[tid] = mn;
            sc_st[tid] = __expf(mo - mn);
        }
        __syncthreads();

#pragma unroll
        for (int mt = 0; mt < 2; mt++) {
#pragma unroll
            for (int h = 0; h < 2; h++) {
                const int r = wm * 32 + mt * 16 + lane4 + 8 * h;
                const float m = m_st[r];
                float s = 0.f;
#pragma unroll
                for (int nt = 0; nt < 4; nt++) {
                    float e0 = __expf(accs[mt][nt][2 * h] - m);
                    float e1 = __expf(accs[mt][nt][2 * h + 1] - m);
                    s += e0 + e1;
                    const int cg = wn * 32 + nt * 8 + 2 * lanek;  // kv col 0..255
                    const int kc = cg >> 6, cw = cg & 63;
                    uint32_t off = (uint32_t)(kc * 8192 + r * 128 +
                                   (((cw >> 3) * 16) ^ ((r & 7) * 16)) + (cw & 7) * 2);
                    *(uint32_t*)(smem + SM_P + off) = f22h(e0, e1);
                }
                s += __shfl_xor_sync(0xffffffffu, s, 1);
                s += __shfl_xor_sync(0xffffffffu, s, 2);
                if (lanek == 0) psum[wn * 64 + r] = s;
                const float scl = sc_st[r];
#pragma unroll
                for (int nt = 0; nt < 4; nt++) {
                    acco[mt][nt][2 * h]     *= scl;
                    acco[mt][nt][2 * h + 1] *= scl;
                }
            }
        }
        __syncthreads();
        if (tid < QT) {
            float s = 0.f;
#pragma unroll
            for (int g = 0; g < 8; g++) s += psum[g * 64 + tid];
            l_st[tid] = l_st[tid] * sc_st[tid] + s;
        }

        // ============== PV phase: O += P @ Vj  (4 kv-chunks) ===============
        for (int d = 0; d < 4; ++d) {
            CP_WAIT1();
            __syncthreads();
            const uint32_t aT = sb + SM_P + d * 8192;
            const uint32_t bT = sb + SM_V + (d & 1) * 32768;
#pragma unroll
            for (int kk = 0; kk < 4; ++kk) {
                uint32_t af[2][4], bf[2][4];
#pragma unroll
                for (int mt = 0; mt < 2; ++mt)
                    ldm4(af[mt], ldm_addr(aT, wm * 32 + mt * 16, kk, lane));
#pragma unroll
                for (int nb = 0; nb < 2; ++nb)
                    ldm4(bf[nb], ldm_addr(bT, wn * 32 + nb * 16, kk, lane));
#pragma unroll
                for (int mt = 0; mt < 2; ++mt)
#pragma unroll
                    for (int n8 = 0; n8 < 4; ++n8)
                        mma16(acco[mt][n8], af[mt],
                              bf[n8 >> 1][n8 & 1], bf[n8 >> 1][2 + (n8 & 1)]);
            }
            __syncthreads();
            if (d < 2) {
                // V kv-chunk d+2 -> vbuf (d&1)
#pragma unroll
                for (int i = 0; i < 4; i++) {
                    int f = tid + i * 512, r = f >> 3, c16 = f & 7;
                    uint32_t dst = sb + SM_V + (d & 1) * 32768 +
                                   (uint32_t)(r * 128 + ((c16 * 16) ^ ((r & 7) * 16)));
                    cpa16(dst, vtb + (long)r * T_ + j * KT2 + (d + 2) * 64 + c16 * 8);
                }
            } else {
                // K d-chunk d-2 of next tile -> kbuf (d-2)
                const int jn = (j + 1) & (NT2 - 1);
#pragma unroll
                for (int i = 0; i < 4; i++) {
                    int f = tid + i * 512, r = f >> 3, c16 = f & 7;
                    uint32_t dst = sb + SM_K + (d - 2) * 32768 +
                                   (uint32_t)(r * 128 + ((c16 * 16) ^ ((r & 7) * 16)));
                    cpa16(dst, kb + (long)(jn * KT2 + r) * P_ + (d - 2) * 64 + c16 * 8);
                }
            }
            CP_COMMIT();
        }
    }

    CP_WAIT0();
    __syncthreads();

    // ---- epilogue: O / l -> g_attn [T,B,P] fp32
#pragma unroll
    for (int mt = 0; mt < 2; mt++) {
#pragma unroll
        for (int h = 0; h < 2; h++) {
            const int r = wm * 32 + mt * 16 + lane4 + 8 * h;
            const float inv = 1.0f / l_st[r];
            const long base = ((long)(t0 + r) * B_ + bz) * P_;
#pragma unroll
            for (int nt = 0; nt < 4; nt++) {
                const int gc = wn * 32 + nt * 8 + 2 * lanek;
                *(float2*)(g_attn + base + gc) =
                    make_float2(acco[mt][nt][2 * h] * inv, acco[mt][nt][2 * h + 1] * inv);
            }
        }
    }
}

// ---------------------------------------------------------------------------
extern "C" void kernel_launch(void* const* d_in, const int* in_sizes, int n_in,
                              void* d_out, int out_size)
{
    const float* query = (const float*)d_in[0];   // [T,B,D]
    const float* W_kqv = (const float*)d_in[1];   // [D, 3P]
    const float* b_kqv = (const float*)d_in[2];   // [3P]
    const float* W_out = (const float*)d_in[3];   // [P, O]
    const float* b_out = (const float*)d_in[4];   // [O]
    float* out = (float*)d_out;                   // [T,B,O]

    __half *v, *vT, *wkqvT, *woutT;
    float *at;
    cudaGetSymbolAddress((void**)&v,     g_v);
    cudaGetSymbolAddress((void**)&vT,    g_vT);
    cudaGetSymbolAddress((void**)&at,    g_attn);
    cudaGetSymbolAddress((void**)&wkqvT, g_wkqvT);
    cudaGetSymbolAddress((void**)&woutT, g_woutT);

    cudaFuncSetAttribute(gemm_h<1>, cudaFuncAttributeMaxDynamicSharedMemorySize, SMG_BYTES);
    cudaFuncSetAttribute(gemm_h<3>, cudaFuncAttributeMaxDynamicSharedMemorySize, SMG_BYTES);
    cudaFuncSetAttribute(flash_attn, cudaFuncAttributeMaxDynamicSharedMemorySize, SMF_BYTES);

    const long sQKV = (long)T_ * P_;
    const dim3 tb(32, 8);

    // 0) weights -> [N,K] K-major fp16
    transpose_t<float, __half><<<dim3(3 * P_ / 32, D_ / 32, 1), tb>>>(W_kqv, wkqvT, D_, 3 * P_, 0, 0);
    transpose_t<float, __half><<<dim3(O_ / 32, P_ / 32, 1), tb>>>(W_out, woutT, P_, O_, 0, 0);

    // 1) QKV projection + split/scale -> g_q/g_k/g_v fp16
    gemm_h<1><<<dim3(6, 256, 1), 256, SMG_BYTES>>>(
        query, wkqvT, nullptr, D_, D_, D_, 0, b_kqv);

    // 2) v -> vT [B,P,T] fp16
    transpose_t<__half, __half><<<dim3(P_ / 32, T_ / 32, B_), tb>>>(v, vT, T_, P_, sQKV, (long)P_ * T_);

    // 3) fused flash attention (512 threads, 16 warps) -> g_attn fp32
    flash_attn<<<dim3(T_ / QT, B_), 512, SMF_BYTES>>>();

    // 4) out = attn @ woutT^T + b_out
    gemm_h<3><<<dim3(2, 256, 1), 256, SMG_BYTES>>>(
        at, woutT, out, P_, P_, P_, O_, b_out);
}